// round 10
// baseline (speedup 1.0000x reference)
#include <cuda_runtime.h>
#include <math.h>
#include <stdint.h>

#define T_DIM 8192
#define D_DIM 512

// Scratch (allocation-free rule: __device__ globals)
__device__ float g_hnorm[T_DIM * D_DIM];
__device__ float g_q[T_DIM * D_DIM];
__device__ float g_k[T_DIM * D_DIM];
__device__ float g_vt[T_DIM * D_DIM];          // V transposed: [d][T]
__device__ float g_avp[4][T_DIM * D_DIM];      // PV split-K partials
__device__ float g_wr[4][D_DIM * D_DIM];       // tf32-rounded weights (q,k,v,o)
__device__ float g_S[(size_t)T_DIM * T_DIM];   // 256 MB score matrix

// ===========================================================================
// Helpers
// ===========================================================================
__device__ __forceinline__ uint32_t smem_u32(const void* p) {
    uint32_t a;
    asm("{ .reg .u64 t; cvta.to.shared.u64 t, %1; cvt.u32.u64 %0, t; }" : "=r"(a) : "l"(p));
    return a;
}
__device__ __forceinline__ float rnd_tf32(float f) {
    uint32_t r;
    asm("cvt.rna.tf32.f32 %0, %1;" : "=r"(r) : "f"(f));
    return __uint_as_float(r);
}
#define SW128(o) ((o) ^ ((((uint32_t)(o)) >> 3) & 0x70))

#define CP_ASYNC16(dst, src) \
    asm volatile("cp.async.cg.shared.global [%0], [%1], 16;" :: "r"(dst), "l"(src) : "memory")
#define CP_COMMIT() asm volatile("cp.async.commit_group;" ::: "memory")
#define CP_WAIT1()  asm volatile("cp.async.wait_group 1;" ::: "memory")

__device__ __forceinline__ void ldsm_x4(uint32_t& r0, uint32_t& r1, uint32_t& r2, uint32_t& r3,
                                        uint32_t addr) {
    asm volatile("ldmatrix.sync.aligned.m8n8.x4.shared.b16 {%0,%1,%2,%3}, [%4];"
                 : "=r"(r0), "=r"(r1), "=r"(r2), "=r"(r3) : "r"(addr));
}

__device__ __forceinline__ void mma_tf32(float* c, const uint32_t* a, const uint32_t* b) {
    asm volatile(
        "mma.sync.aligned.m16n8k8.row.col.f32.tf32.tf32.f32 "
        "{%0,%1,%2,%3}, {%4,%5,%6,%7}, {%8,%9}, {%0,%1,%2,%3};"
        : "+f"(c[0]), "+f"(c[1]), "+f"(c[2]), "+f"(c[3])
        : "r"(a[0]), "r"(a[1]), "r"(a[2]), "r"(a[3]),
          "r"(b[0]), "r"(b[1]));
}

// ===========================================================================
// LayerNorm (one block/row, 128 thr, tf32-rounded output).
// Blocks 0..1023 additionally round the 4 weight matrices into g_wr.
// ===========================================================================
__global__ void ln_kernel(const float* __restrict__ h,
                          const float* __restrict__ w,
                          const float* __restrict__ b,
                          float* __restrict__ out,
                          const float* __restrict__ w0,
                          const float* __restrict__ w1,
                          const float* __restrict__ w2,
                          const float* __restrict__ w3,
                          float* __restrict__ wr)
{
    int row = blockIdx.x;
    int t = threadIdx.x;

    // side job: weight rounding (first 1024 blocks, 2 float4 per thread)
    if (row < 1024) {
        #pragma unroll
        for (int j = 0; j < 2; j++) {
            int idx = row * 256 + j * 128 + t;      // float4 index, 0..262143
            int mat = idx >> 16;                    // 65536 float4 per matrix
            int off = idx & 65535;
            const float* src = (mat == 0) ? w0 : (mat == 1) ? w1
                             : (mat == 2) ? w2 : w3;
            float4 v = ((const float4*)src)[off];
            float4 o;
            o.x = rnd_tf32(v.x); o.y = rnd_tf32(v.y);
            o.z = rnd_tf32(v.z); o.w = rnd_tf32(v.w);
            ((float4*)wr)[(size_t)mat * 65536 + off] = o;
        }
    }

    const float4* hr = (const float4*)(h + (size_t)row * D_DIM);
    float4 x = hr[t];
    float s  = x.x + x.y + x.z + x.w;
    float ss = x.x * x.x + x.y * x.y + x.z * x.z + x.w * x.w;

    #pragma unroll
    for (int o = 16; o; o >>= 1) {
        s  += __shfl_xor_sync(0xffffffffu, s,  o);
        ss += __shfl_xor_sync(0xffffffffu, ss, o);
    }
    __shared__ float red[2][4];
    int lane = t & 31, warp = t >> 5;
    if (lane == 0) { red[0][warp] = s; red[1][warp] = ss; }
    __syncthreads();
    float a = red[0][0] + red[0][1] + red[0][2] + red[0][3];
    float c = red[1][0] + red[1][1] + red[1][2] + red[1][3];
    float mean = a * (1.0f / D_DIM);
    float var  = c * (1.0f / D_DIM) - mean * mean;
    float rstd = rsqrtf(var + 1e-5f);

    float4 wv = ((const float4*)w)[t];
    float4 bv = ((const float4*)b)[t];
    float4 o;
    o.x = rnd_tf32((x.x - mean) * rstd * wv.x + bv.x);
    o.y = rnd_tf32((x.y - mean) * rstd * wv.y + bv.y);
    o.z = rnd_tf32((x.z - mean) * rstd * wv.z + bv.z);
    o.w = rnd_tf32((x.w - mean) * rstd * wv.w + bv.w);
    ((float4*)(out + (size_t)row * D_DIM))[t] = o;
}

// ===========================================================================
// TF32 mma.sync GEMM (NT): C = scale*(A[M,K] @ B[N,K]^T) (+res)
// 128x128x32 block tile, 4 warps (2x2), warp tile 64x64, 2 CTA/SM.
// 3-stage cp.async ring, SW128 swizzle, ldmatrix frags.
//   TRI:     1-D triangular grid; decode blockIdx.x -> (by, bx), bx <= by
//   CAPK:    cap k-loop at m0+128 (PV); also reverses y-order (big CTAs first)
//   ROUND:   round outputs to tf32 grid
//   RES:     add residual
//   KSPLIT>0: split capped k-range across blockIdx.z, raw partial to
//             C + z*M*ldc
//   QKV:     blockIdx.z in {0,1,2} selects weight B+z*D*D and output
//             {C, C2, C3}; z==2 writes transposed (vt, row stride ldct)
//   SUM4:    A operand = rnd_tf32(sum of 4 partials at A + j*M*lda)
// ===========================================================================
#define BK 32
#define TILE_B (128 * BK * 4)    // 16 KB per tile buffer
#define NSTAGE 3
#define SM_A 0
#define SM_B (NSTAGE * TILE_B)
#define SM_TOT (2 * NSTAGE * TILE_B)   // 96 KB

template<int TRI, int CAPK, int ROUND, int RES, int KSPLIT, int QKV, int SUM4>
__global__ void __launch_bounds__(128, 2)
gemm_nt_tc(const float* __restrict__ A,
           const float* __restrict__ B,
           float* __restrict__ C,
           float* __restrict__ C2,
           float* __restrict__ C3,
           const float* __restrict__ res,
           int M, int N, int K,
           int lda, int ldb, int ldc, int ldct,
           float scale)
{
    extern __shared__ char smem[];
    int m0, n0;
    if (TRI) {
        // triangular decode: idx = by*(by+1)/2 + bx, bx <= by
        int idx = blockIdx.x;
        int by = (int)((sqrtf(8.0f * (float)idx + 1.0f) - 1.0f) * 0.5f);
        while ((by + 1) * (by + 2) / 2 <= idx) by++;
        while (by * (by + 1) / 2 > idx) by--;
        int bx = idx - by * (by + 1) / 2;
        m0 = by * 128;
        n0 = bx * 128;
    } else {
        int yb = CAPK ? ((int)gridDim.y - 1 - (int)blockIdx.y) : (int)blockIdx.y;
        m0 = yb * 128;
        n0 = blockIdx.x * 128;
    }

    const float* Bp = B;
    float* Cp = C;
    int ldcw = ldc;
    int zq = 0;
    if (QKV) {
        zq = blockIdx.z;
        Bp = B + (size_t)zq * D_DIM * D_DIM;
        Cp = (zq == 0) ? C : (zq == 1) ? C2 : C3;
        if (zq == 2) ldcw = ldct;
    }

    uint32_t sbase = smem_u32(smem);
    int t    = threadIdx.x;          // 0..127
    int lane = t & 31;
    int warp = t >> 5;               // 0..3
    int gid  = lane >> 2;
    int tig  = lane & 3;
    int wm   = (warp >> 1) * 64;     // 0,64
    int wn   = (warp & 1) * 64;      // 0,64

    int kend  = CAPK ? min(K, m0 + 128) : K;
    int iters = kend / BK;
    int it0 = 0, it1 = iters;
    if (KSPLIT > 0) {
        int z = blockIdx.z;
        it0 = (iters * z) / KSPLIT;
        it1 = (iters * (z + 1)) / KSPLIT;
        Cp = C + (size_t)z * M * ldc;
    }
    int niter = it1 - it0;

    auto load_tiles = [&](int buf, int k0) {
        if (SUM4) {
            #pragma unroll
            for (int i = 0; i < 8; i++) {
                int f = t + i * 128;
                int row = f >> 3, kg = f & 7;
                size_t gidx = (size_t)(m0 + row) * lda + k0 + kg * 4;
                float4 s0 = *(const float4*)(A + gidx);
                float4 s1 = *(const float4*)(A + (size_t)M * lda + gidx);
                float4 s2 = *(const float4*)(A + 2 * (size_t)M * lda + gidx);
                float4 s3 = *(const float4*)(A + 3 * (size_t)M * lda + gidx);
                float4 o;
                o.x = rnd_tf32((s0.x + s1.x) + (s2.x + s3.x));
                o.y = rnd_tf32((s0.y + s1.y) + (s2.y + s3.y));
                o.z = rnd_tf32((s0.z + s1.z) + (s2.z + s3.z));
                o.w = rnd_tf32((s0.w + s1.w) + (s2.w + s3.w));
                uint32_t off = SW128((uint32_t)(row * 128 + kg * 16));
                *(float4*)(smem + SM_A + buf * TILE_B + off) = o;
            }
        } else {
            #pragma unroll
            for (int i = 0; i < 8; i++) {
                int f = t + i * 128;
                int row = f >> 3, kg = f & 7;
                uint32_t off = SW128((uint32_t)(row * 128 + kg * 16));
                CP_ASYNC16(sbase + SM_A + buf * TILE_B + off,
                           A + (size_t)(m0 + row) * lda + k0 + kg * 4);
            }
        }
        #pragma unroll
        for (int i = 0; i < 8; i++) {
            int f = t + i * 128;
            int row = f >> 3, kg = f & 7;
            uint32_t off = SW128((uint32_t)(row * 128 + kg * 16));
            CP_ASYNC16(sbase + SM_B + buf * TILE_B + off,
                       Bp + (size_t)(n0 + row) * ldb + k0 + kg * 4);
        }
    };

    float acc[4][8][4];
    #pragma unroll
    for (int mi = 0; mi < 4; mi++)
        #pragma unroll
        for (int ni = 0; ni < 8; ni++)
            #pragma unroll
            for (int r = 0; r < 4; r++) acc[mi][ni][r] = 0.0f;

    // per-thread ldmatrix address components
    int q   = lane >> 3;
    int r8  = lane & 7;
    int aq1 = (q & 1) * 8;
    int aq2 = q >> 1;
    int bq1 = (q >> 1) * 8;
    int bq2 = q & 1;

    load_tiles(0, it0 * BK);
    CP_COMMIT();
    if (niter > 1) load_tiles(1, (it0 + 1) * BK);
    CP_COMMIT();

    int buf = 0;
    for (int it = 0; it < niter; it++) {
        CP_WAIT1();
        __syncthreads();

        uint32_t sa = sbase + SM_A + buf * TILE_B;
        uint32_t sb = sbase + SM_B + buf * TILE_B;

        int nx = it + 2;
        int nbuf = buf + 2; if (nbuf >= NSTAGE) nbuf -= NSTAGE;
        if (nx < niter) load_tiles(nbuf, (it0 + nx) * BK);
        CP_COMMIT();

        #pragma unroll
        for (int ks = 0; ks < BK / 8; ks++) {
            uint32_t afr[4][4];
            #pragma unroll
            for (int mi = 0; mi < 4; mi++) {
                int row = wm + mi * 16 + aq1 + r8;
                int kg  = 2 * ks + aq2;
                uint32_t addr = sa + (uint32_t)(row * 128) + (uint32_t)((kg ^ r8) * 16);
                ldsm_x4(afr[mi][0], afr[mi][1], afr[mi][2], afr[mi][3], addr);
            }
            uint32_t bfr[8][2];
            #pragma unroll
            for (int p = 0; p < 4; p++) {
                int row = wn + p * 16 + bq1 + r8;
                int kg  = 2 * ks + bq2;
                uint32_t addr = sb + (uint32_t)(row * 128) + (uint32_t)((kg ^ r8) * 16);
                uint32_t r0, r1, r2, r3;
                ldsm_x4(r0, r1, r2, r3, addr);
                bfr[2 * p][0] = r0; bfr[2 * p][1] = r1;
                bfr[2 * p + 1][0] = r2; bfr[2 * p + 1][1] = r3;
            }
            #pragma unroll
            for (int mi = 0; mi < 4; mi++)
                #pragma unroll
                for (int ni = 0; ni < 8; ni++)
                    mma_tf32(acc[mi][ni], afr[mi], bfr[ni]);
        }

        buf++; if (buf >= NSTAGE) buf = 0;
    }

    if (QKV && zq == 2) {
        // Transposed output: stage tile transposed in smem, coalesced float4
        // writes of C[n][m] rows. Rounded to tf32 grid.
        __syncthreads();
        float* st = (float*)smem;        // 128 x stride 132
        #pragma unroll
        for (int mi = 0; mi < 4; mi++) {
            #pragma unroll
            for (int ni = 0; ni < 8; ni++) {
                int row = wm + mi * 16 + gid;
                int col = wn + ni * 8 + tig * 2;
                st[(col + 0) * 132 + row]     = rnd_tf32(acc[mi][ni][0]);
                st[(col + 1) * 132 + row]     = rnd_tf32(acc[mi][ni][1]);
                st[(col + 0) * 132 + row + 8] = rnd_tf32(acc[mi][ni][2]);
                st[(col + 1) * 132 + row + 8] = rnd_tf32(acc[mi][ni][3]);
            }
        }
        __syncthreads();
        #pragma unroll
        for (int i = 0; i < 32; i++) {
            int idx = t + i * 128;
            int d = idx >> 5;
            int j = idx & 31;
            float4 o = *(float4*)&st[d * 132 + 4 * j];
            *(float4*)(Cp + (size_t)(n0 + d) * ldcw + m0 + 4 * j) = o;
        }
        return;
    }

    // normal epilogue
    #pragma unroll
    for (int mi = 0; mi < 4; mi++) {
        #pragma unroll
        for (int ni = 0; ni < 8; ni++) {
            int row = m0 + wm + mi * 16 + gid;
            int col = n0 + wn + ni * 8 + tig * 2;
            float2 o0, o1;
            o0.x = acc[mi][ni][0]; o0.y = acc[mi][ni][1];
            o1.x = acc[mi][ni][2]; o1.y = acc[mi][ni][3];
            if (!KSPLIT) {
                o0.x *= scale; o0.y *= scale; o1.x *= scale; o1.y *= scale;
            }
            size_t i0 = (size_t)row * ldcw + col;
            size_t i1 = (size_t)(row + 8) * ldcw + col;
            if (RES) {
                float2 r0 = *(const float2*)(res + i0);
                float2 r1 = *(const float2*)(res + i1);
                o0.x += r0.x; o0.y += r0.y;
                o1.x += r1.x; o1.y += r1.y;
            }
            if (ROUND) {
                o0.x = rnd_tf32(o0.x); o0.y = rnd_tf32(o0.y);
                o1.x = rnd_tf32(o1.x); o1.y = rnd_tf32(o1.y);
            }
            *(float2*)(Cp + i0) = o0;
            *(float2*)(Cp + i1) = o1;
        }
    }
}

// ===========================================================================
// Causal row softmax over S (in place), float4 + __expf.
// Chunk-level early exit: only ceil((row&~127 + 128)/1024) chunks of 1024
// elements are touched; full chunks run unpredicated, only the boundary
// chunk masks. Probs rounded to tf32 grid; zero-pads to the 128-block cap.
// ===========================================================================
__device__ __forceinline__ float block_reduce(float v, bool is_max)
{
    __shared__ float sm[8];
    __syncthreads();
    #pragma unroll
    for (int o = 16; o; o >>= 1) {
        float u = __shfl_xor_sync(0xffffffffu, v, o);
        v = is_max ? fmaxf(v, u) : (v + u);
    }
    int lane = threadIdx.x & 31, warp = threadIdx.x >> 5;
    if (lane == 0) sm[warp] = v;
    __syncthreads();
    float r = sm[0];
    #pragma unroll
    for (int i = 1; i < 8; i++)
        r = is_max ? fmaxf(r, sm[i]) : (r + sm[i]);
    return r;
}

__global__ void softmax_causal(float* __restrict__ S)
{
    int row = blockIdx.x;
    int t = threadIdx.x;               // 0..255
    int n = row + 1;                   // valid length
    int zend = ((row & ~127) + 128);   // zero-pad cap (= PV k-cap for this block)
    int nit = (zend + 1023) >> 10;     // active chunks of 1024 elements
    float4* Srow = (float4*)(S + (size_t)row * T_DIM);

    float4 v[8];
    float mx = -INFINITY;
    #pragma unroll
    for (int it = 0; it < 8; it++) {
        if (it >= nit) break;
        float4 x = Srow[(it << 8) + t];
        v[it] = x;
        if ((it << 10) + 1024 <= n) {
            mx = fmaxf(mx, fmaxf(fmaxf(x.x, x.y), fmaxf(x.z, x.w)));
        } else {
            int j0 = ((it << 8) + t) << 2;
            if (j0 < n)     mx = fmaxf(mx, x.x);
            if (j0 + 1 < n) mx = fmaxf(mx, x.y);
            if (j0 + 2 < n) mx = fmaxf(mx, x.z);
            if (j0 + 3 < n) mx = fmaxf(mx, x.w);
        }
    }
    mx = block_reduce(mx, true);

    float sum = 0.0f;
    #pragma unroll
    for (int it = 0; it < 8; it++) {
        if (it >= nit) break;
        float4 x = v[it];
        if ((it << 10) + 1024 <= n) {
            x.x = __expf(x.x - mx);
            x.y = __expf(x.y - mx);
            x.z = __expf(x.z - mx);
            x.w = __expf(x.w - mx);
        } else {
            int j0 = ((it << 8) + t) << 2;
            x.x = (j0 < n)     ? __expf(x.x - mx) : 0.0f;
            x.y = (j0 + 1 < n) ? __expf(x.y - mx) : 0.0f;
            x.z = (j0 + 2 < n) ? __expf(x.z - mx) : 0.0f;
            x.w = (j0 + 3 < n) ? __expf(x.w - mx) : 0.0f;
        }
        v[it] = x;
        sum += (x.x + x.y) + (x.z + x.w);
    }
    sum = block_reduce(sum, false);
    float inv = 1.0f / sum;

    #pragma unroll
    for (int it = 0; it < 8; it++) {
        if (it >= nit) break;
        int j0 = ((it << 8) + t) << 2;
        if (j0 < zend) {
            float4 x = v[it];
            float4 o;
            o.x = rnd_tf32(x.x * inv);
            o.y = rnd_tf32(x.y * inv);
            o.z = rnd_tf32(x.z * inv);
            o.w = rnd_tf32(x.w * inv);
            Srow[(it << 8) + t] = o;
        }
    }
}

// ===========================================================================
extern "C" void kernel_launch(void* const* d_in, const int* in_sizes, int n_in,
                              void* d_out, int out_size)
{
    const float* h    = (const float*)d_in[0];
    const float* ln_w = (const float*)d_in[1];
    const float* ln_b = (const float*)d_in[2];
    const float* w_q  = (const float*)d_in[3];
    const float* w_k  = (const float*)d_in[4];
    const float* w_v  = (const float*)d_in[5];
    const float* w_o  = (const float*)d_in[6];
    float* out = (float*)d_out;

    float *hn, *q, *k, *vt, *avp, *S, *wr;
    cudaGetSymbolAddress((void**)&hn,  g_hnorm);
    cudaGetSymbolAddress((void**)&q,   g_q);
    cudaGetSymbolAddress((void**)&k,   g_k);
    cudaGetSymbolAddress((void**)&vt,  g_vt);
    cudaGetSymbolAddress((void**)&avp, g_avp);
    cudaGetSymbolAddress((void**)&S,   g_S);
    cudaGetSymbolAddress((void**)&wr,  g_wr);
    float* wo_r = wr + 3 * (size_t)D_DIM * D_DIM;

    cudaFuncSetAttribute((const void*)gemm_nt_tc<0,0,1,0,0,1,0>,
                         cudaFuncAttributeMaxDynamicSharedMemorySize, SM_TOT);
    cudaFuncSetAttribute((const void*)gemm_nt_tc<1,0,0,0,0,0,0>,
                         cudaFuncAttributeMaxDynamicSharedMemorySize, SM_TOT);
    cudaFuncSetAttribute((const void*)gemm_nt_tc<0,1,0,0,4,0,0>,
                         cudaFuncAttributeMaxDynamicSharedMemorySize, SM_TOT);
    cudaFuncSetAttribute((const void*)gemm_nt_tc<0,0,0,1,0,0,1>,
                         cudaFuncAttributeMaxDynamicSharedMemorySize, SM_TOT);

    const float inv_sqrt_d = 0.044194173824159216f;  // 1/sqrt(512)

    // 1) LayerNorm (+ fused weight rounding into g_wr)
    ln_kernel<<<T_DIM, 128>>>(h, ln_w, ln_b, hn, w_q, w_k, w_v, w_o, wr);

    // 2) Q, K, V projections in ONE launch (z selects; z=2 writes vt transposed)
    dim3 gQKV(D_DIM / 128, T_DIM / 128, 3);  // (4, 64, 3) = 768 CTAs
    gemm_nt_tc<0,0,1,0,0,1,0><<<gQKV, 128, SM_TOT>>>(hn, wr, q, k, vt, nullptr,
        T_DIM, D_DIM, D_DIM, D_DIM, D_DIM, D_DIM, T_DIM, 1.0f);

    // 3) Scores = Q @ K^T * 1/sqrt(d), triangular 1-D grid (2080 working CTAs)
    int nblk = T_DIM / 128;                       // 64
    dim3 gScore(nblk * (nblk + 1) / 2);           // 2080
    gemm_nt_tc<1,0,0,0,0,0,0><<<gScore, 128, SM_TOT>>>(q, k, S, nullptr, nullptr, nullptr,
        T_DIM, T_DIM, D_DIM, D_DIM, D_DIM, T_DIM, 0, inv_sqrt_d);

    // 4) Causal softmax (chunk-level early exit, rounded probs, zero-pad to cap)
    softmax_causal<<<T_DIM, 256>>>(S);

    // 5) AV partials = softmax(S) @ Vt^T (NT, k-capped, split-K4, big CTAs first)
    dim3 gPV(D_DIM / 128, T_DIM / 128, 4);  // (4, 64, 4) = 1024 CTAs
    gemm_nt_tc<0,1,0,0,4,0,0><<<gPV, 128, SM_TOT>>>(S, vt, avp, nullptr, nullptr, nullptr,
        T_DIM, D_DIM, T_DIM, T_DIM, T_DIM, D_DIM, 0, 1.0f);

    // 6) out = h + rnd(sum of 4 partials) @ W_o^T (fused reduce in A loader)
    dim3 gProj(D_DIM / 128, T_DIM / 128);  // (4, 64)
    gemm_nt_tc<0,0,0,1,0,0,1><<<gProj, 128, SM_TOT>>>(avp, wo_r, out, nullptr, nullptr, h,
        T_DIM, D_DIM, D_DIM, D_DIM, D_DIM, D_DIM, 0, 1.0f);
}

// round 11
// speedup vs baseline: 1.0286x; 1.0286x over previous
#include <cuda_runtime.h>
#include <math.h>
#include <stdint.h>

#define T_DIM 8192
#define D_DIM 512

// Scratch (allocation-free rule: __device__ globals)
__device__ float g_hnorm[T_DIM * D_DIM];
__device__ float g_q[T_DIM * D_DIM];
__device__ float g_k[T_DIM * D_DIM];
__device__ float g_vt[T_DIM * D_DIM];          // V transposed: [d][T]
__device__ float g_avp[4][T_DIM * D_DIM];      // PV split-K partials
__device__ float g_wr[4][D_DIM * D_DIM];       // tf32-rounded weights (q,k,v,o)
__device__ float g_S[(size_t)T_DIM * T_DIM];   // 256 MB score matrix

// ===========================================================================
// Helpers
// ===========================================================================
__device__ __forceinline__ uint32_t smem_u32(const void* p) {
    uint32_t a;
    asm("{ .reg .u64 t; cvta.to.shared.u64 t, %1; cvt.u32.u64 %0, t; }" : "=r"(a) : "l"(p));
    return a;
}
__device__ __forceinline__ float rnd_tf32(float f) {
    uint32_t r;
    asm("cvt.rna.tf32.f32 %0, %1;" : "=r"(r) : "f"(f));
    return __uint_as_float(r);
}
#define SW128(o) ((o) ^ ((((uint32_t)(o)) >> 3) & 0x70))

#define CP_ASYNC16(dst, src) \
    asm volatile("cp.async.cg.shared.global [%0], [%1], 16;" :: "r"(dst), "l"(src) : "memory")
#define CP_COMMIT() asm volatile("cp.async.commit_group;" ::: "memory")
#define CP_WAIT1()  asm volatile("cp.async.wait_group 1;" ::: "memory")

__device__ __forceinline__ void ldsm_x4(uint32_t& r0, uint32_t& r1, uint32_t& r2, uint32_t& r3,
                                        uint32_t addr) {
    asm volatile("ldmatrix.sync.aligned.m8n8.x4.shared.b16 {%0,%1,%2,%3}, [%4];"
                 : "=r"(r0), "=r"(r1), "=r"(r2), "=r"(r3) : "r"(addr));
}

__device__ __forceinline__ void mma_tf32(float* c, const uint32_t* a, const uint32_t* b) {
    asm volatile(
        "mma.sync.aligned.m16n8k8.row.col.f32.tf32.tf32.f32 "
        "{%0,%1,%2,%3}, {%4,%5,%6,%7}, {%8,%9}, {%0,%1,%2,%3};"
        : "+f"(c[0]), "+f"(c[1]), "+f"(c[2]), "+f"(c[3])
        : "r"(a[0]), "r"(a[1]), "r"(a[2]), "r"(a[3]),
          "r"(b[0]), "r"(b[1]));
}

// ===========================================================================
// LayerNorm (one block/row, 128 thr, tf32-rounded output).
// Blocks 0..1023 additionally round the 4 weight matrices into g_wr.
// ===========================================================================
__global__ void ln_kernel(const float* __restrict__ h,
                          const float* __restrict__ w,
                          const float* __restrict__ b,
                          float* __restrict__ out,
                          const float* __restrict__ w0,
                          const float* __restrict__ w1,
                          const float* __restrict__ w2,
                          const float* __restrict__ w3,
                          float* __restrict__ wr)
{
    int row = blockIdx.x;
    int t = threadIdx.x;

    // side job: weight rounding (first 1024 blocks, 2 float4 per thread)
    if (row < 1024) {
        #pragma unroll
        for (int j = 0; j < 2; j++) {
            int idx = row * 256 + j * 128 + t;      // float4 index, 0..262143
            int mat = idx >> 16;                    // 65536 float4 per matrix
            int off = idx & 65535;
            const float* src = (mat == 0) ? w0 : (mat == 1) ? w1
                             : (mat == 2) ? w2 : w3;
            float4 v = ((const float4*)src)[off];
            float4 o;
            o.x = rnd_tf32(v.x); o.y = rnd_tf32(v.y);
            o.z = rnd_tf32(v.z); o.w = rnd_tf32(v.w);
            ((float4*)wr)[(size_t)mat * 65536 + off] = o;
        }
    }

    const float4* hr = (const float4*)(h + (size_t)row * D_DIM);
    float4 x = hr[t];
    float s  = x.x + x.y + x.z + x.w;
    float ss = x.x * x.x + x.y * x.y + x.z * x.z + x.w * x.w;

    #pragma unroll
    for (int o = 16; o; o >>= 1) {
        s  += __shfl_xor_sync(0xffffffffu, s,  o);
        ss += __shfl_xor_sync(0xffffffffu, ss, o);
    }
    __shared__ float red[2][4];
    int lane = t & 31, warp = t >> 5;
    if (lane == 0) { red[0][warp] = s; red[1][warp] = ss; }
    __syncthreads();
    float a = red[0][0] + red[0][1] + red[0][2] + red[0][3];
    float c = red[1][0] + red[1][1] + red[1][2] + red[1][3];
    float mean = a * (1.0f / D_DIM);
    float var  = c * (1.0f / D_DIM) - mean * mean;
    float rstd = rsqrtf(var + 1e-5f);

    float4 wv = ((const float4*)w)[t];
    float4 bv = ((const float4*)b)[t];
    float4 o;
    o.x = rnd_tf32((x.x - mean) * rstd * wv.x + bv.x);
    o.y = rnd_tf32((x.y - mean) * rstd * wv.y + bv.y);
    o.z = rnd_tf32((x.z - mean) * rstd * wv.z + bv.z);
    o.w = rnd_tf32((x.w - mean) * rstd * wv.w + bv.w);
    ((float4*)(out + (size_t)row * D_DIM))[t] = o;
}

// ===========================================================================
// TF32 mma.sync GEMM (NT): C = scale*(A[M,K] @ B[N,K]^T) (+res)
// 128x128x32 block tile, 4 warps (2x2), warp tile 64x64, 2 CTA/SM.
// 3-stage cp.async ring, SW128 swizzle, ldmatrix frags.
//   CAUSAL:  skip blocks fully above diagonal
//   CAPK:    cap k-loop at m0+128 (PV); also reverses y-order (big CTAs first)
//   ROUND:   round outputs to tf32 grid
//   RES:     add residual
//   KSPLIT>0: split capped k-range across blockIdx.z, raw partial to
//             C + z*M*ldc
//   QKV:     blockIdx.z in {0,1,2} selects weight B+z*D*D and output
//             {C, C2, C3}; z==2 writes transposed (vt, row stride ldct)
//   SUM4:    A operand = rnd_tf32(sum of 4 partials at A + j*M*lda)
// ===========================================================================
#define BK 32
#define TILE_B (128 * BK * 4)    // 16 KB per tile buffer
#define NSTAGE 3
#define SM_A 0
#define SM_B (NSTAGE * TILE_B)
#define SM_TOT (2 * NSTAGE * TILE_B)   // 96 KB

template<int CAUSAL, int CAPK, int ROUND, int RES, int KSPLIT, int QKV, int SUM4>
__global__ void __launch_bounds__(128, 2)
gemm_nt_tc(const float* __restrict__ A,
           const float* __restrict__ B,
           float* __restrict__ C,
           float* __restrict__ C2,
           float* __restrict__ C3,
           const float* __restrict__ res,
           int M, int N, int K,
           int lda, int ldb, int ldc, int ldct,
           float scale)
{
    extern __shared__ char smem[];
    int yb = CAPK ? ((int)gridDim.y - 1 - (int)blockIdx.y) : (int)blockIdx.y;
    int m0 = yb * 128;
    int n0 = blockIdx.x * 128;
    if (CAUSAL && n0 > m0 + 127) return;

    const float* Bp = B;
    float* Cp = C;
    int ldcw = ldc;
    int zq = 0;
    if (QKV) {
        zq = blockIdx.z;
        Bp = B + (size_t)zq * D_DIM * D_DIM;
        Cp = (zq == 0) ? C : (zq == 1) ? C2 : C3;
        if (zq == 2) ldcw = ldct;
    }

    uint32_t sbase = smem_u32(smem);
    int t    = threadIdx.x;          // 0..127
    int lane = t & 31;
    int warp = t >> 5;               // 0..3
    int gid  = lane >> 2;
    int tig  = lane & 3;
    int wm   = (warp >> 1) * 64;     // 0,64
    int wn   = (warp & 1) * 64;      // 0,64

    int kend  = CAPK ? min(K, m0 + 128) : K;
    int iters = kend / BK;
    int it0 = 0, it1 = iters;
    if (KSPLIT > 0) {
        int z = blockIdx.z;
        it0 = (iters * z) / KSPLIT;
        it1 = (iters * (z + 1)) / KSPLIT;
        Cp = C + (size_t)z * M * ldc;
    }
    int niter = it1 - it0;

    auto load_tiles = [&](int buf, int k0) {
        if (SUM4) {
            #pragma unroll
            for (int i = 0; i < 8; i++) {
                int f = t + i * 128;
                int row = f >> 3, kg = f & 7;
                size_t gidx = (size_t)(m0 + row) * lda + k0 + kg * 4;
                float4 s0 = *(const float4*)(A + gidx);
                float4 s1 = *(const float4*)(A + (size_t)M * lda + gidx);
                float4 s2 = *(const float4*)(A + 2 * (size_t)M * lda + gidx);
                float4 s3 = *(const float4*)(A + 3 * (size_t)M * lda + gidx);
                float4 o;
                o.x = rnd_tf32((s0.x + s1.x) + (s2.x + s3.x));
                o.y = rnd_tf32((s0.y + s1.y) + (s2.y + s3.y));
                o.z = rnd_tf32((s0.z + s1.z) + (s2.z + s3.z));
                o.w = rnd_tf32((s0.w + s1.w) + (s2.w + s3.w));
                uint32_t off = SW128((uint32_t)(row * 128 + kg * 16));
                *(float4*)(smem + SM_A + buf * TILE_B + off) = o;
            }
        } else {
            #pragma unroll
            for (int i = 0; i < 8; i++) {
                int f = t + i * 128;
                int row = f >> 3, kg = f & 7;
                uint32_t off = SW128((uint32_t)(row * 128 + kg * 16));
                CP_ASYNC16(sbase + SM_A + buf * TILE_B + off,
                           A + (size_t)(m0 + row) * lda + k0 + kg * 4);
            }
        }
        #pragma unroll
        for (int i = 0; i < 8; i++) {
            int f = t + i * 128;
            int row = f >> 3, kg = f & 7;
            uint32_t off = SW128((uint32_t)(row * 128 + kg * 16));
            CP_ASYNC16(sbase + SM_B + buf * TILE_B + off,
                       Bp + (size_t)(n0 + row) * ldb + k0 + kg * 4);
        }
    };

    float acc[4][8][4];
    #pragma unroll
    for (int mi = 0; mi < 4; mi++)
        #pragma unroll
        for (int ni = 0; ni < 8; ni++)
            #pragma unroll
            for (int r = 0; r < 4; r++) acc[mi][ni][r] = 0.0f;

    // per-thread ldmatrix address components
    int q   = lane >> 3;
    int r8  = lane & 7;
    int aq1 = (q & 1) * 8;
    int aq2 = q >> 1;
    int bq1 = (q >> 1) * 8;
    int bq2 = q & 1;

    load_tiles(0, it0 * BK);
    CP_COMMIT();
    if (niter > 1) load_tiles(1, (it0 + 1) * BK);
    CP_COMMIT();

    int buf = 0;
    for (int it = 0; it < niter; it++) {
        CP_WAIT1();
        __syncthreads();

        uint32_t sa = sbase + SM_A + buf * TILE_B;
        uint32_t sb = sbase + SM_B + buf * TILE_B;

        int nx = it + 2;
        int nbuf = buf + 2; if (nbuf >= NSTAGE) nbuf -= NSTAGE;
        if (nx < niter) load_tiles(nbuf, (it0 + nx) * BK);
        CP_COMMIT();

        #pragma unroll
        for (int ks = 0; ks < BK / 8; ks++) {
            uint32_t afr[4][4];
            #pragma unroll
            for (int mi = 0; mi < 4; mi++) {
                int row = wm + mi * 16 + aq1 + r8;
                int kg  = 2 * ks + aq2;
                uint32_t addr = sa + (uint32_t)(row * 128) + (uint32_t)((kg ^ r8) * 16);
                ldsm_x4(afr[mi][0], afr[mi][1], afr[mi][2], afr[mi][3], addr);
            }
            uint32_t bfr[8][2];
            #pragma unroll
            for (int p = 0; p < 4; p++) {
                int row = wn + p * 16 + bq1 + r8;
                int kg  = 2 * ks + bq2;
                uint32_t addr = sb + (uint32_t)(row * 128) + (uint32_t)((kg ^ r8) * 16);
                uint32_t r0, r1, r2, r3;
                ldsm_x4(r0, r1, r2, r3, addr);
                bfr[2 * p][0] = r0; bfr[2 * p][1] = r1;
                bfr[2 * p + 1][0] = r2; bfr[2 * p + 1][1] = r3;
            }
            #pragma unroll
            for (int mi = 0; mi < 4; mi++)
                #pragma unroll
                for (int ni = 0; ni < 8; ni++)
                    mma_tf32(acc[mi][ni], afr[mi], bfr[ni]);
        }

        buf++; if (buf >= NSTAGE) buf = 0;
    }

    if (QKV && zq == 2) {
        // Transposed output: stage tile transposed in smem, coalesced float4
        // writes of C[n][m] rows. Rounded to tf32 grid.
        __syncthreads();
        float* st = (float*)smem;        // 128 x stride 132
        #pragma unroll
        for (int mi = 0; mi < 4; mi++) {
            #pragma unroll
            for (int ni = 0; ni < 8; ni++) {
                int row = wm + mi * 16 + gid;
                int col = wn + ni * 8 + tig * 2;
                st[(col + 0) * 132 + row]     = rnd_tf32(acc[mi][ni][0]);
                st[(col + 1) * 132 + row]     = rnd_tf32(acc[mi][ni][1]);
                st[(col + 0) * 132 + row + 8] = rnd_tf32(acc[mi][ni][2]);
                st[(col + 1) * 132 + row + 8] = rnd_tf32(acc[mi][ni][3]);
            }
        }
        __syncthreads();
        #pragma unroll
        for (int i = 0; i < 32; i++) {
            int idx = t + i * 128;
            int d = idx >> 5;
            int j = idx & 31;
            float4 o = *(float4*)&st[d * 132 + 4 * j];
            *(float4*)(Cp + (size_t)(n0 + d) * ldcw + m0 + 4 * j) = o;
        }
        return;
    }

    // normal epilogue
    #pragma unroll
    for (int mi = 0; mi < 4; mi++) {
        #pragma unroll
        for (int ni = 0; ni < 8; ni++) {
            int row = m0 + wm + mi * 16 + gid;
            int col = n0 + wn + ni * 8 + tig * 2;
            float2 o0, o1;
            o0.x = acc[mi][ni][0]; o0.y = acc[mi][ni][1];
            o1.x = acc[mi][ni][2]; o1.y = acc[mi][ni][3];
            if (!KSPLIT) {
                o0.x *= scale; o0.y *= scale; o1.x *= scale; o1.y *= scale;
            }
            size_t i0 = (size_t)row * ldcw + col;
            size_t i1 = (size_t)(row + 8) * ldcw + col;
            if (RES) {
                float2 r0 = *(const float2*)(res + i0);
                float2 r1 = *(const float2*)(res + i1);
                o0.x += r0.x; o0.y += r0.y;
                o1.x += r1.x; o1.y += r1.y;
            }
            if (ROUND) {
                o0.x = rnd_tf32(o0.x); o0.y = rnd_tf32(o0.y);
                o1.x = rnd_tf32(o1.x); o1.y = rnd_tf32(o1.y);
            }
            *(float2*)(Cp + i0) = o0;
            *(float2*)(Cp + i1) = o1;
        }
    }
}

// ===========================================================================
// Causal row softmax over S (in place), float4 + __expf.
// Chunk skipping via PREDICATION (no breaks): all 8 iterations unrolled,
// loads @p-guarded so active ones front-batch (MLP preserved). Only the
// boundary chunk masks per element. Probs tf32-rounded; zero-pad to cap.
// ===========================================================================
__device__ __forceinline__ float block_reduce(float v, bool is_max)
{
    __shared__ float sm[8];
    __syncthreads();
    #pragma unroll
    for (int o = 16; o; o >>= 1) {
        float u = __shfl_xor_sync(0xffffffffu, v, o);
        v = is_max ? fmaxf(v, u) : (v + u);
    }
    int lane = threadIdx.x & 31, warp = threadIdx.x >> 5;
    if (lane == 0) sm[warp] = v;
    __syncthreads();
    float r = sm[0];
    #pragma unroll
    for (int i = 1; i < 8; i++)
        r = is_max ? fmaxf(r, sm[i]) : (r + sm[i]);
    return r;
}

__global__ void softmax_causal(float* __restrict__ S)
{
    int row = blockIdx.x;
    int t = threadIdx.x;               // 0..255
    int n = row + 1;                   // valid length
    int zend = (row & ~127) + 128;     // zero-pad cap (= PV k-cap)
    int nit = zend >> 10;              // count of FULLY ACTIVE 1024-chunks may
                                       // undercount; recompute precisely:
    nit = (zend + 1023) >> 10;         // active chunks
    float4* Srow = (float4*)(S + (size_t)row * T_DIM);

    float4 v[8];
    float mx = -INFINITY;
    #pragma unroll
    for (int it = 0; it < 8; it++) {
        bool active = (it < nit);
        float4 x = make_float4(-INFINITY, -INFINITY, -INFINITY, -INFINITY);
        if (active) x = Srow[(it << 8) + t];           // @p load, batchable
        v[it] = x;
        if ((it << 10) + 1024 <= n) {                  // fully valid chunk
            mx = fmaxf(mx, fmaxf(fmaxf(x.x, x.y), fmaxf(x.z, x.w)));
        } else if (active) {                            // boundary chunk
            int j0 = ((it << 8) + t) << 2;
            if (j0 < n)     mx = fmaxf(mx, x.x);
            if (j0 + 1 < n) mx = fmaxf(mx, x.y);
            if (j0 + 2 < n) mx = fmaxf(mx, x.z);
            if (j0 + 3 < n) mx = fmaxf(mx, x.w);
        }
    }
    mx = block_reduce(mx, true);

    float sum = 0.0f;
    #pragma unroll
    for (int it = 0; it < 8; it++) {
        bool active = (it < nit);
        float4 x = v[it];
        if ((it << 10) + 1024 <= n) {
            x.x = __expf(x.x - mx);
            x.y = __expf(x.y - mx);
            x.z = __expf(x.z - mx);
            x.w = __expf(x.w - mx);
            v[it] = x;
            sum += (x.x + x.y) + (x.z + x.w);
        } else if (active) {
            int j0 = ((it << 8) + t) << 2;
            x.x = (j0 < n)     ? __expf(x.x - mx) : 0.0f;
            x.y = (j0 + 1 < n) ? __expf(x.y - mx) : 0.0f;
            x.z = (j0 + 2 < n) ? __expf(x.z - mx) : 0.0f;
            x.w = (j0 + 3 < n) ? __expf(x.w - mx) : 0.0f;
            v[it] = x;
            sum += (x.x + x.y) + (x.z + x.w);
        }
    }
    sum = block_reduce(sum, false);
    float inv = 1.0f / sum;

    #pragma unroll
    for (int it = 0; it < 8; it++) {
        if (it < nit) {
            float4 x = v[it];
            float4 o;
            o.x = rnd_tf32(x.x * inv);
            o.y = rnd_tf32(x.y * inv);
            o.z = rnd_tf32(x.z * inv);
            o.w = rnd_tf32(x.w * inv);
            Srow[(it << 8) + t] = o;                   // @p store
        }
    }
}

// ===========================================================================
extern "C" void kernel_launch(void* const* d_in, const int* in_sizes, int n_in,
                              void* d_out, int out_size)
{
    const float* h    = (const float*)d_in[0];
    const float* ln_w = (const float*)d_in[1];
    const float* ln_b = (const float*)d_in[2];
    const float* w_q  = (const float*)d_in[3];
    const float* w_k  = (const float*)d_in[4];
    const float* w_v  = (const float*)d_in[5];
    const float* w_o  = (const float*)d_in[6];
    float* out = (float*)d_out;

    float *hn, *q, *k, *vt, *avp, *S, *wr;
    cudaGetSymbolAddress((void**)&hn,  g_hnorm);
    cudaGetSymbolAddress((void**)&q,   g_q);
    cudaGetSymbolAddress((void**)&k,   g_k);
    cudaGetSymbolAddress((void**)&vt,  g_vt);
    cudaGetSymbolAddress((void**)&avp, g_avp);
    cudaGetSymbolAddress((void**)&S,   g_S);
    cudaGetSymbolAddress((void**)&wr,  g_wr);
    float* wo_r = wr + 3 * (size_t)D_DIM * D_DIM;

    cudaFuncSetAttribute((const void*)gemm_nt_tc<0,0,1,0,0,1,0>,
                         cudaFuncAttributeMaxDynamicSharedMemorySize, SM_TOT);
    cudaFuncSetAttribute((const void*)gemm_nt_tc<1,0,0,0,0,0,0>,
                         cudaFuncAttributeMaxDynamicSharedMemorySize, SM_TOT);
    cudaFuncSetAttribute((const void*)gemm_nt_tc<0,1,0,0,4,0,0>,
                         cudaFuncAttributeMaxDynamicSharedMemorySize, SM_TOT);
    cudaFuncSetAttribute((const void*)gemm_nt_tc<0,0,0,1,0,0,1>,
                         cudaFuncAttributeMaxDynamicSharedMemorySize, SM_TOT);

    const float inv_sqrt_d = 0.044194173824159216f;  // 1/sqrt(512)

    // 1) LayerNorm (+ fused weight rounding into g_wr)
    ln_kernel<<<T_DIM, 128>>>(h, ln_w, ln_b, hn, w_q, w_k, w_v, w_o, wr);

    // 2) Q, K, V projections in ONE launch (z selects; z=2 writes vt transposed)
    dim3 gQKV(D_DIM / 128, T_DIM / 128, 3);  // (4, 64, 3) = 768 CTAs
    gemm_nt_tc<0,0,1,0,0,1,0><<<gQKV, 128, SM_TOT>>>(hn, wr, q, k, vt, nullptr,
        T_DIM, D_DIM, D_DIM, D_DIM, D_DIM, D_DIM, T_DIM, 1.0f);

    // 3) Scores = Q @ K^T * 1/sqrt(d), lower-tri blocks only (NT, causal)
    dim3 gScore(T_DIM / 128, T_DIM / 128);  // (64, 64)
    gemm_nt_tc<1,0,0,0,0,0,0><<<gScore, 128, SM_TOT>>>(q, k, S, nullptr, nullptr, nullptr,
        T_DIM, T_DIM, D_DIM, D_DIM, D_DIM, T_DIM, 0, inv_sqrt_d);

    // 4) Causal softmax (predicated chunk skipping, rounded probs)
    softmax_causal<<<T_DIM, 256>>>(S);

    // 5) AV partials = softmax(S) @ Vt^T (NT, k-capped, split-K4, big CTAs first)
    dim3 gPV(D_DIM / 128, T_DIM / 128, 4);  // (4, 64, 4) = 1024 CTAs
    gemm_nt_tc<0,1,0,0,4,0,0><<<gPV, 128, SM_TOT>>>(S, vt, avp, nullptr, nullptr, nullptr,
        T_DIM, D_DIM, T_DIM, T_DIM, T_DIM, D_DIM, 0, 1.0f);

    // 6) out = h + rnd(sum of 4 partials) @ W_o^T (fused reduce in A loader)
    dim3 gProj(D_DIM / 128, T_DIM / 128);  // (4, 64)
    gemm_nt_tc<0,0,0,1,0,0,1><<<gProj, 128, SM_TOT>>>(avp, wo_r, out, nullptr, nullptr, h,
        T_DIM, D_DIM, D_DIM, D_DIM, D_DIM, D_DIM, 0, 1.0f);
}

// round 12
// speedup vs baseline: 1.7302x; 1.6821x over previous
#include <cuda_runtime.h>
#include <cuda_fp16.h>
#include <math.h>
#include <stdint.h>

#define T_DIM 8192
#define D_DIM 512

// Scratch (allocation-free rule: __device__ globals)
__device__ __half g_hnorm[T_DIM * D_DIM];
__device__ __half g_q[T_DIM * D_DIM];
__device__ __half g_k[T_DIM * D_DIM];
__device__ __half g_vt[T_DIM * D_DIM];            // V transposed: [d][T]
__device__ float  g_avp[4][T_DIM * D_DIM];        // PV split-K partials (fp32)
__device__ __half g_wr[4][D_DIM * D_DIM];         // fp16-rounded weights (q,k,v,o)
__device__ __half g_S[(size_t)T_DIM * T_DIM];     // 128 MB score/prob matrix

// ===========================================================================
// Helpers
// ===========================================================================
__device__ __forceinline__ uint32_t smem_u32(const void* p) {
    uint32_t a;
    asm("{ .reg .u64 t; cvta.to.shared.u64 t, %1; cvt.u32.u64 %0, t; }" : "=r"(a) : "l"(p));
    return a;
}
__device__ __forceinline__ uint32_t pack_h2(float a, float b) {
    __half2 h = __floats2half2_rn(a, b);
    return *(uint32_t*)&h;
}
#define SW128(o) ((o) ^ ((((uint32_t)(o)) >> 3) & 0x70))

#define CP_ASYNC16(dst, src) \
    asm volatile("cp.async.cg.shared.global [%0], [%1], 16;" :: "r"(dst), "l"(src) : "memory")
#define CP_COMMIT() asm volatile("cp.async.commit_group;" ::: "memory")
#define CP_WAIT1()  asm volatile("cp.async.wait_group 1;" ::: "memory")

__device__ __forceinline__ void ldsm_x4(uint32_t& r0, uint32_t& r1, uint32_t& r2, uint32_t& r3,
                                        uint32_t addr) {
    asm volatile("ldmatrix.sync.aligned.m8n8.x4.shared.b16 {%0,%1,%2,%3}, [%4];"
                 : "=r"(r0), "=r"(r1), "=r"(r2), "=r"(r3) : "r"(addr));
}

// fp16 MMA, fp32 accumulate: m16n8k16
__device__ __forceinline__ void mma_f16(float* c, const uint32_t* a, const uint32_t* b) {
    asm volatile(
        "mma.sync.aligned.m16n8k16.row.col.f32.f16.f16.f32 "
        "{%0,%1,%2,%3}, {%4,%5,%6,%7}, {%8,%9}, {%0,%1,%2,%3};"
        : "+f"(c[0]), "+f"(c[1]), "+f"(c[2]), "+f"(c[3])
        : "r"(a[0]), "r"(a[1]), "r"(a[2]), "r"(a[3]),
          "r"(b[0]), "r"(b[1]));
}

// ===========================================================================
// LayerNorm (one block/row, 128 thr) -> fp16 output.
// Blocks 0..1023 additionally round the 4 weight matrices into g_wr (fp16).
// ===========================================================================
__global__ void ln_kernel(const float* __restrict__ h,
                          const float* __restrict__ w,
                          const float* __restrict__ b,
                          __half* __restrict__ out,
                          const float* __restrict__ w0,
                          const float* __restrict__ w1,
                          const float* __restrict__ w2,
                          const float* __restrict__ w3,
                          __half* __restrict__ wr)
{
    int row = blockIdx.x;
    int t = threadIdx.x;

    // side job: weight fp16 rounding (first 1024 blocks, 2 float4 per thread)
    if (row < 1024) {
        #pragma unroll
        for (int j = 0; j < 2; j++) {
            int idx = row * 256 + j * 128 + t;      // float4 index, 0..262143
            int mat = idx >> 16;                    // 65536 float4 per matrix
            int off = idx & 65535;
            const float* src = (mat == 0) ? w0 : (mat == 1) ? w1
                             : (mat == 2) ? w2 : w3;
            float4 v = ((const float4*)src)[off];
            uint2 u;
            u.x = pack_h2(v.x, v.y);
            u.y = pack_h2(v.z, v.w);
            ((uint2*)wr)[(size_t)mat * 65536 + off] = u;
        }
    }

    const float4* hr = (const float4*)(h + (size_t)row * D_DIM);
    float4 x = hr[t];
    float s  = x.x + x.y + x.z + x.w;
    float ss = x.x * x.x + x.y * x.y + x.z * x.z + x.w * x.w;

    #pragma unroll
    for (int o = 16; o; o >>= 1) {
        s  += __shfl_xor_sync(0xffffffffu, s,  o);
        ss += __shfl_xor_sync(0xffffffffu, ss, o);
    }
    __shared__ float red[2][4];
    int lane = t & 31, warp = t >> 5;
    if (lane == 0) { red[0][warp] = s; red[1][warp] = ss; }
    __syncthreads();
    float a = red[0][0] + red[0][1] + red[0][2] + red[0][3];
    float c = red[1][0] + red[1][1] + red[1][2] + red[1][3];
    float mean = a * (1.0f / D_DIM);
    float var  = c * (1.0f / D_DIM) - mean * mean;
    float rstd = rsqrtf(var + 1e-5f);

    float4 wv = ((const float4*)w)[t];
    float4 bv = ((const float4*)b)[t];
    uint2 u;
    u.x = pack_h2((x.x - mean) * rstd * wv.x + bv.x,
                  (x.y - mean) * rstd * wv.y + bv.y);
    u.y = pack_h2((x.z - mean) * rstd * wv.z + bv.z,
                  (x.w - mean) * rstd * wv.w + bv.w);
    *(uint2*)(out + (size_t)row * D_DIM + t * 4) = u;
}

// ===========================================================================
// FP16 mma.sync GEMM (NT): C = scale*(A[M,K] @ B[N,K]^T) (+res)
// 128x128x64 block tile (128B rows = 64 halves), 4 warps (2x2), warp 64x64,
// 2 CTA/SM. 3-stage cp.async ring, SW128 swizzle, ldmatrix b16 frags,
// m16n8k16 fp16 MMA with fp32 accumulate. Operand rounding happens at the
// producers (__float2half_rn), so MMA math is exact on the fp16 grid.
//   CAUSAL:  skip blocks fully above diagonal
//   CAPK:    cap k-loop at m0+128 (PV); reverses y-order (big CTAs first)
//   OUTH:    output fp16 (feeds another MMA); else fp32
//   RES:     add fp32 residual (final output)
//   KSPLIT>0: split capped k-range across blockIdx.z, raw fp32 partial to
//             Cf + z*M*ldc
//   QKV:     blockIdx.z in {0,1,2} selects weight B+z*D*D and output
//             {Ch, C2h, C3h}; z==2 writes transposed (vt, row stride ldct)
//   SUM4:    A operand = half(sum of 4 fp32 partials at A4 + j*M*lda)
// ===========================================================================
#define BK 64
#define TILE_B (128 * 128)       // 16 KB per tile buffer (128 rows x 128 B)
#define NSTAGE 3
#define SM_A 0
#define SM_B (NSTAGE * TILE_B)
#define SM_TOT (2 * NSTAGE * TILE_B)   // 96 KB

template<int CAUSAL, int CAPK, int OUTH, int RES, int KSPLIT, int QKV, int SUM4>
__global__ void __launch_bounds__(128, 2)
gemm_f16(const __half* __restrict__ A,
         const float* __restrict__ A4,
         const __half* __restrict__ B,
         __half* __restrict__ Ch,
         __half* __restrict__ C2h,
         __half* __restrict__ C3h,
         float* __restrict__ Cf,
         const float* __restrict__ res,
         int M, int N, int K,
         int lda, int ldb, int ldc, int ldct,
         float scale)
{
    extern __shared__ char smem[];
    int yb = CAPK ? ((int)gridDim.y - 1 - (int)blockIdx.y) : (int)blockIdx.y;
    int m0 = yb * 128;
    int n0 = blockIdx.x * 128;
    if (CAUSAL && n0 > m0 + 127) return;

    const __half* Bp = B;
    __half* Chp = Ch;
    float* Cfp = Cf;
    int ldcw = ldc;
    int zq = 0;
    if (QKV) {
        zq = blockIdx.z;
        Bp = B + (size_t)zq * D_DIM * D_DIM;
        Chp = (zq == 0) ? Ch : (zq == 1) ? C2h : C3h;
        if (zq == 2) ldcw = ldct;
    }

    uint32_t sbase = smem_u32(smem);
    int t    = threadIdx.x;          // 0..127
    int lane = t & 31;
    int warp = t >> 5;               // 0..3
    int gid  = lane >> 2;
    int tig  = lane & 3;
    int wm   = (warp >> 1) * 64;     // 0,64
    int wn   = (warp & 1) * 64;      // 0,64

    int kend  = CAPK ? min(K, m0 + 128) : K;
    int iters = kend / BK;
    int it0 = 0, it1 = iters;
    if (KSPLIT > 0) {
        int z = blockIdx.z;
        it0 = (iters * z) / KSPLIT;
        it1 = (iters * (z + 1)) / KSPLIT;
        Cfp = Cf + (size_t)z * M * ldc;
    }
    int niter = it1 - it0;

    // loaders: 128 rows x 128 bytes per tile; 8 x 16B chunks per thread.
    // 16 B = 8 halves; kg indexes 16B groups (8 per row).
    auto load_tiles = [&](int buf, int k0) {
        if (SUM4) {
            #pragma unroll
            for (int i = 0; i < 8; i++) {
                int f = t + i * 128;
                int row = f >> 3, kg = f & 7;
                size_t g0 = (size_t)(m0 + row) * lda + k0 + kg * 8;
                const float4* p0 = (const float4*)(A4 + g0);
                const float4* p1 = (const float4*)(A4 + (size_t)M * lda + g0);
                const float4* p2 = (const float4*)(A4 + 2 * (size_t)M * lda + g0);
                const float4* p3 = (const float4*)(A4 + 3 * (size_t)M * lda + g0);
                float4 a0 = p0[0], b0 = p0[1];
                float4 a1 = p1[0], b1 = p1[1];
                float4 a2 = p2[0], b2 = p2[1];
                float4 a3 = p3[0], b3 = p3[1];
                uint4 u;
                u.x = pack_h2((a0.x + a1.x) + (a2.x + a3.x),
                              (a0.y + a1.y) + (a2.y + a3.y));
                u.y = pack_h2((a0.z + a1.z) + (a2.z + a3.z),
                              (a0.w + a1.w) + (a2.w + a3.w));
                u.z = pack_h2((b0.x + b1.x) + (b2.x + b3.x),
                              (b0.y + b1.y) + (b2.y + b3.y));
                u.w = pack_h2((b0.z + b1.z) + (b2.z + b3.z),
                              (b0.w + b1.w) + (b2.w + b3.w));
                uint32_t off = SW128((uint32_t)(row * 128 + kg * 16));
                *(uint4*)(smem + SM_A + buf * TILE_B + off) = u;
            }
        } else {
            #pragma unroll
            for (int i = 0; i < 8; i++) {
                int f = t + i * 128;
                int row = f >> 3, kg = f & 7;
                uint32_t off = SW128((uint32_t)(row * 128 + kg * 16));
                CP_ASYNC16(sbase + SM_A + buf * TILE_B + off,
                           A + (size_t)(m0 + row) * lda + k0 + kg * 8);
            }
        }
        #pragma unroll
        for (int i = 0; i < 8; i++) {
            int f = t + i * 128;
            int row = f >> 3, kg = f & 7;
            uint32_t off = SW128((uint32_t)(row * 128 + kg * 16));
            CP_ASYNC16(sbase + SM_B + buf * TILE_B + off,
                       Bp + (size_t)(n0 + row) * ldb + k0 + kg * 8);
        }
    };

    float acc[4][8][4];
    #pragma unroll
    for (int mi = 0; mi < 4; mi++)
        #pragma unroll
        for (int ni = 0; ni < 8; ni++)
            #pragma unroll
            for (int r = 0; r < 4; r++) acc[mi][ni][r] = 0.0f;

    // per-thread ldmatrix address components (identical byte math to tf32 ver)
    int q   = lane >> 3;
    int r8  = lane & 7;
    int aq1 = (q & 1) * 8;        // A: +8 rows for matrices 1,3 (a1,a3)
    int aq2 = q >> 1;             // A: kgroup +1 for matrices 2,3 (a2,a3)
    int bq1 = (q >> 1) * 8;       // B: second n-subtile for matrices 2,3
    int bq2 = q & 1;              // B: kgroup +1 for matrices 1,3

    load_tiles(0, it0 * BK);
    CP_COMMIT();
    if (niter > 1) load_tiles(1, (it0 + 1) * BK);
    CP_COMMIT();

    int buf = 0;
    for (int it = 0; it < niter; it++) {
        CP_WAIT1();
        __syncthreads();

        uint32_t sa = sbase + SM_A + buf * TILE_B;
        uint32_t sb = sbase + SM_B + buf * TILE_B;

        int nx = it + 2;
        int nbuf = buf + 2; if (nbuf >= NSTAGE) nbuf -= NSTAGE;
        if (nx < niter) load_tiles(nbuf, (it0 + nx) * BK);
        CP_COMMIT();

        // 4 k16 slices per 64-deep tile; each slice spans 2 kgroups (32 B)
        #pragma unroll
        for (int ks = 0; ks < BK / 16; ks++) {
            uint32_t afr[4][4];
            #pragma unroll
            for (int mi = 0; mi < 4; mi++) {
                int row = wm + mi * 16 + aq1 + r8;
                int kg  = 2 * ks + aq2;
                uint32_t addr = sa + (uint32_t)(row * 128) + (uint32_t)((kg ^ r8) * 16);
                ldsm_x4(afr[mi][0], afr[mi][1], afr[mi][2], afr[mi][3], addr);
            }
            uint32_t bfr[8][2];
            #pragma unroll
            for (int p = 0; p < 4; p++) {
                int row = wn + p * 16 + bq1 + r8;
                int kg  = 2 * ks + bq2;
                uint32_t addr = sb + (uint32_t)(row * 128) + (uint32_t)((kg ^ r8) * 16);
                uint32_t r0, r1, r2, r3;
                ldsm_x4(r0, r1, r2, r3, addr);
                bfr[2 * p][0] = r0; bfr[2 * p][1] = r1;
                bfr[2 * p + 1][0] = r2; bfr[2 * p + 1][1] = r3;
            }
            #pragma unroll
            for (int mi = 0; mi < 4; mi++)
                #pragma unroll
                for (int ni = 0; ni < 8; ni++)
                    mma_f16(acc[mi][ni], afr[mi], bfr[ni]);
        }

        buf++; if (buf >= NSTAGE) buf = 0;
    }

    if (QKV && zq == 2) {
        // Transposed fp16 output (vt): stage fp32 tile transposed in smem,
        // then coalesced 16B writes of 8 halves along m.
        __syncthreads();
        float* st = (float*)smem;        // 128 x stride 132
        #pragma unroll
        for (int mi = 0; mi < 4; mi++) {
            #pragma unroll
            for (int ni = 0; ni < 8; ni++) {
                int row = wm + mi * 16 + gid;
                int col = wn + ni * 8 + tig * 2;
                st[(col + 0) * 132 + row]     = acc[mi][ni][0];
                st[(col + 1) * 132 + row]     = acc[mi][ni][1];
                st[(col + 0) * 132 + row + 8] = acc[mi][ni][2];
                st[(col + 1) * 132 + row + 8] = acc[mi][ni][3];
            }
        }
        __syncthreads();
        #pragma unroll
        for (int i = 0; i < 16; i++) {
            int idx = t + i * 128;       // 2048 chunks of 8 halves
            int d = idx >> 4;            // output row (n-dim), 0..127
            int j = idx & 15;            // 8-half chunk along m
            const float* sp = &st[d * 132 + j * 8];
            uint4 u;
            u.x = pack_h2(sp[0], sp[1]);
            u.y = pack_h2(sp[2], sp[3]);
            u.z = pack_h2(sp[4], sp[5]);
            u.w = pack_h2(sp[6], sp[7]);
            *(uint4*)(Chp + (size_t)(n0 + d) * ldcw + m0 + j * 8) = u;
        }
        return;
    }

    if (OUTH) {
        // fp16 output (q, k, scores): scale then round-to-nearest fp16
        #pragma unroll
        for (int mi = 0; mi < 4; mi++) {
            #pragma unroll
            for (int ni = 0; ni < 8; ni++) {
                int row = m0 + wm + mi * 16 + gid;
                int col = n0 + wn + ni * 8 + tig * 2;
                uint32_t u0 = pack_h2(acc[mi][ni][0] * scale, acc[mi][ni][1] * scale);
                uint32_t u1 = pack_h2(acc[mi][ni][2] * scale, acc[mi][ni][3] * scale);
                *(uint32_t*)(Chp + (size_t)row * ldcw + col) = u0;
                *(uint32_t*)(Chp + (size_t)(row + 8) * ldcw + col) = u1;
            }
        }
        return;
    }

    // fp32 output (PV partials raw / final with residual)
    #pragma unroll
    for (int mi = 0; mi < 4; mi++) {
        #pragma unroll
        for (int ni = 0; ni < 8; ni++) {
            int row = m0 + wm + mi * 16 + gid;
            int col = n0 + wn + ni * 8 + tig * 2;
            float2 o0, o1;
            o0.x = acc[mi][ni][0]; o0.y = acc[mi][ni][1];
            o1.x = acc[mi][ni][2]; o1.y = acc[mi][ni][3];
            size_t i0 = (size_t)row * ldcw + col;
            size_t i1 = (size_t)(row + 8) * ldcw + col;
            if (RES) {
                float2 r0 = *(const float2*)(res + i0);
                float2 r1 = *(const float2*)(res + i1);
                o0.x += r0.x; o0.y += r0.y;
                o1.x += r1.x; o1.y += r1.y;
            }
            *(float2*)(Cfp + i0) = o0;
            *(float2*)(Cfp + i1) = o1;
        }
    }
}

// ===========================================================================
// Causal row softmax over fp16 S (in place). 256 thr/row; 4 chunks of 2048
// elements (8 halves per thread per chunk). Chunk skipping via predication
// (loads stay front-batched). Probs written as fp16 (rn) = operand rounding.
// Zero-pads [n, zend) where zend = (row & ~127) + 128 = PV's k-cap.
// ===========================================================================
__device__ __forceinline__ float block_reduce(float v, bool is_max)
{
    __shared__ float sm[8];
    __syncthreads();
    #pragma unroll
    for (int o = 16; o; o >>= 1) {
        float u = __shfl_xor_sync(0xffffffffu, v, o);
        v = is_max ? fmaxf(v, u) : (v + u);
    }
    int lane = threadIdx.x & 31, warp = threadIdx.x >> 5;
    if (lane == 0) sm[warp] = v;
    __syncthreads();
    float r = sm[0];
    #pragma unroll
    for (int i = 1; i < 8; i++)
        r = is_max ? fmaxf(r, sm[i]) : (r + sm[i]);
    return r;
}

__global__ void softmax_causal(__half* __restrict__ S)
{
    int row = blockIdx.x;
    int t = threadIdx.x;                 // 0..255
    int n = row + 1;                     // valid length
    int zend = (row & ~127) + 128;       // zero-pad cap (= PV k-cap)
    int nit = (zend + 2047) >> 11;       // active 2048-chunks (1..4)
    uint4* Srow = (uint4*)(S + (size_t)row * T_DIM);   // 8 halves per uint4

    float x[4][8];
    float mx = -INFINITY;
    #pragma unroll
    for (int it = 0; it < 4; it++) {
        bool active = (it < nit);
        uint4 u = make_uint4(0, 0, 0, 0);
        if (active) u = Srow[(it << 8) + t];
        float2 f0 = __half22float2(*(__half2*)&u.x);
        float2 f1 = __half22float2(*(__half2*)&u.y);
        float2 f2 = __half22float2(*(__half2*)&u.z);
        float2 f3 = __half22float2(*(__half2*)&u.w);
        x[it][0] = f0.x; x[it][1] = f0.y; x[it][2] = f1.x; x[it][3] = f1.y;
        x[it][4] = f2.x; x[it][5] = f2.y; x[it][6] = f3.x; x[it][7] = f3.y;
        int j0 = (it << 11) + t * 8;
        if ((it << 11) + 2048 <= n) {                 // fully valid chunk
            #pragma unroll
            for (int e = 0; e < 8; e++) mx = fmaxf(mx, x[it][e]);
        } else if (active) {                           // boundary chunk
            #pragma unroll
            for (int e = 0; e < 8; e++)
                if (j0 + e < n) mx = fmaxf(mx, x[it][e]);
        }
    }
    mx = block_reduce(mx, true);

    float sum = 0.0f;
    #pragma unroll
    for (int it = 0; it < 4; it++) {
        bool active = (it < nit);
        int j0 = (it << 11) + t * 8;
        if ((it << 11) + 2048 <= n) {
            #pragma unroll
            for (int e = 0; e < 8; e++) {
                x[it][e] = __expf(x[it][e] - mx);
                sum += x[it][e];
            }
        } else if (active) {
            #pragma unroll
            for (int e = 0; e < 8; e++) {
                x[it][e] = (j0 + e < n) ? __expf(x[it][e] - mx) : 0.0f;
                sum += x[it][e];
            }
        }
    }
    sum = block_reduce(sum, false);
    float inv = 1.0f / sum;

    #pragma unroll
    for (int it = 0; it < 4; it++) {
        int j0 = (it << 11) + t * 8;
        if (it < nit && j0 < zend) {
            uint4 u;
            u.x = pack_h2(x[it][0] * inv, x[it][1] * inv);
            u.y = pack_h2(x[it][2] * inv, x[it][3] * inv);
            u.z = pack_h2(x[it][4] * inv, x[it][5] * inv);
            u.w = pack_h2(x[it][6] * inv, x[it][7] * inv);
            Srow[(it << 8) + t] = u;
        }
    }
}

// ===========================================================================
extern "C" void kernel_launch(void* const* d_in, const int* in_sizes, int n_in,
                              void* d_out, int out_size)
{
    const float* h    = (const float*)d_in[0];
    const float* ln_w = (const float*)d_in[1];
    const float* ln_b = (const float*)d_in[2];
    const float* w_q  = (const float*)d_in[3];
    const float* w_k  = (const float*)d_in[4];
    const float* w_v  = (const float*)d_in[5];
    const float* w_o  = (const float*)d_in[6];
    float* out = (float*)d_out;

    __half *hn, *q, *k, *vt, *S, *wr;
    float *avp;
    cudaGetSymbolAddress((void**)&hn,  g_hnorm);
    cudaGetSymbolAddress((void**)&q,   g_q);
    cudaGetSymbolAddress((void**)&k,   g_k);
    cudaGetSymbolAddress((void**)&vt,  g_vt);
    cudaGetSymbolAddress((void**)&avp, g_avp);
    cudaGetSymbolAddress((void**)&S,   g_S);
    cudaGetSymbolAddress((void**)&wr,  g_wr);
    __half* wo_r = wr + 3 * (size_t)D_DIM * D_DIM;

    cudaFuncSetAttribute((const void*)gemm_f16<0,0,1,0,0,1,0>,
                         cudaFuncAttributeMaxDynamicSharedMemorySize, SM_TOT);
    cudaFuncSetAttribute((const void*)gemm_f16<1,0,1,0,0,0,0>,
                         cudaFuncAttributeMaxDynamicSharedMemorySize, SM_TOT);
    cudaFuncSetAttribute((const void*)gemm_f16<0,1,0,0,4,0,0>,
                         cudaFuncAttributeMaxDynamicSharedMemorySize, SM_TOT);
    cudaFuncSetAttribute((const void*)gemm_f16<0,0,0,1,0,0,1>,
                         cudaFuncAttributeMaxDynamicSharedMemorySize, SM_TOT);

    const float inv_sqrt_d = 0.044194173824159216f;  // 1/sqrt(512)

    // 1) LayerNorm -> fp16 (+ fused fp16 weight rounding)
    ln_kernel<<<T_DIM, 128>>>(h, ln_w, ln_b, hn, w_q, w_k, w_v, w_o, wr);

    // 2) Q, K, V projections in ONE launch (z selects; z=2 writes vt transposed)
    dim3 gQKV(D_DIM / 128, T_DIM / 128, 3);  // (4, 64, 3)
    gemm_f16<0,0,1,0,0,1,0><<<gQKV, 128, SM_TOT>>>(hn, nullptr, wr,
        q, k, vt, nullptr, nullptr,
        T_DIM, D_DIM, D_DIM, D_DIM, D_DIM, D_DIM, T_DIM, 1.0f);

    // 3) Scores = Q @ K^T * 1/sqrt(d) -> fp16 S, lower-tri blocks only
    dim3 gScore(T_DIM / 128, T_DIM / 128);  // (64, 64)
    gemm_f16<1,0,1,0,0,0,0><<<gScore, 128, SM_TOT>>>(q, nullptr, k,
        S, nullptr, nullptr, nullptr, nullptr,
        T_DIM, T_DIM, D_DIM, D_DIM, D_DIM, T_DIM, 0, inv_sqrt_d);

    // 4) Causal softmax (fp16 in/out, predicated chunk skipping)
    softmax_causal<<<T_DIM, 256>>>(S);

    // 5) AV partials = softmax(S) @ Vt^T (k-capped, split-K4, fp32 partials)
    dim3 gPV(D_DIM / 128, T_DIM / 128, 4);  // (4, 64, 4)
    gemm_f16<0,1,0,0,4,0,0><<<gPV, 128, SM_TOT>>>(S, nullptr, vt,
        nullptr, nullptr, nullptr, avp, nullptr,
        T_DIM, D_DIM, T_DIM, T_DIM, T_DIM, D_DIM, 0, 1.0f);

    // 6) out = h + half(sum of 4 partials) @ W_o^T (fused reduce in A loader)
    dim3 gProj(D_DIM / 128, T_DIM / 128);  // (4, 64)
    gemm_f16<0,0,0,1,0,0,1><<<gProj, 128, SM_TOT>>>(nullptr, avp, wo_r,
        nullptr, nullptr, nullptr, out, h,
        T_DIM, D_DIM, D_DIM, D_DIM, D_DIM, D_DIM, 0, 1.0f);
}

// round 13
// speedup vs baseline: 1.9055x; 1.1014x over previous
#include <cuda_runtime.h>
#include <cuda_fp16.h>
#include <math.h>
#include <stdint.h>

#define T_DIM 8192
#define D_DIM 512

// Scratch (allocation-free rule: __device__ globals)
__device__ __half g_hnorm[T_DIM * D_DIM];
__device__ __half g_q[T_DIM * D_DIM];
__device__ __half g_k[T_DIM * D_DIM];
__device__ __half g_vt[T_DIM * D_DIM];            // V'^T : [d][T], V' = hn @ (Wo Wv)^T
__device__ float  g_avp[4][T_DIM * D_DIM];        // PV split-K partials (fp32)
__device__ __half g_wr[4][D_DIM * D_DIM];         // fp16 weights: q, k, (W'), o
__device__ __half g_wvt[D_DIM * D_DIM];           // Wv^T fp16
__device__ __half g_S[(size_t)T_DIM * T_DIM];     // 128 MB score/prob matrix

// ===========================================================================
// Helpers
// ===========================================================================
__device__ __forceinline__ uint32_t smem_u32(const void* p) {
    uint32_t a;
    asm("{ .reg .u64 t; cvta.to.shared.u64 t, %1; cvt.u32.u64 %0, t; }" : "=r"(a) : "l"(p));
    return a;
}
__device__ __forceinline__ uint32_t pack_h2(float a, float b) {
    __half2 h = __floats2half2_rn(a, b);
    return *(uint32_t*)&h;
}
#define SW128(o) ((o) ^ ((((uint32_t)(o)) >> 3) & 0x70))
#define NEG_BIG (-60000.0f)

#define CP_ASYNC16(dst, src) \
    asm volatile("cp.async.cg.shared.global [%0], [%1], 16;" :: "r"(dst), "l"(src) : "memory")
#define CP_COMMIT() asm volatile("cp.async.commit_group;" ::: "memory")
#define CP_WAIT1()  asm volatile("cp.async.wait_group 1;" ::: "memory")

__device__ __forceinline__ void ldsm_x4(uint32_t& r0, uint32_t& r1, uint32_t& r2, uint32_t& r3,
                                        uint32_t addr) {
    asm volatile("ldmatrix.sync.aligned.m8n8.x4.shared.b16 {%0,%1,%2,%3}, [%4];"
                 : "=r"(r0), "=r"(r1), "=r"(r2), "=r"(r3) : "r"(addr));
}

// fp16 MMA, fp32 accumulate: m16n8k16
__device__ __forceinline__ void mma_f16(float* c, const uint32_t* a, const uint32_t* b) {
    asm volatile(
        "mma.sync.aligned.m16n8k16.row.col.f32.f16.f16.f32 "
        "{%0,%1,%2,%3}, {%4,%5,%6,%7}, {%8,%9}, {%0,%1,%2,%3};"
        : "+f"(c[0]), "+f"(c[1]), "+f"(c[2]), "+f"(c[3])
        : "r"(a[0]), "r"(a[1]), "r"(a[2]), "r"(a[3]),
          "r"(b[0]), "r"(b[1]));
}

// ===========================================================================
// LayerNorm (one block/row, 128 thr) -> fp16 output.
// Blocks 0..1023 additionally round the 4 weight matrices into g_wr (fp16).
// (slot 2 = rounded Wv is later overwritten by W' = Wo@Wv.)
// ===========================================================================
__global__ void ln_kernel(const float* __restrict__ h,
                          const float* __restrict__ w,
                          const float* __restrict__ b,
                          __half* __restrict__ out,
                          const float* __restrict__ w0,
                          const float* __restrict__ w1,
                          const float* __restrict__ w2,
                          const float* __restrict__ w3,
                          __half* __restrict__ wr)
{
    int row = blockIdx.x;
    int t = threadIdx.x;

    if (row < 1024) {
        #pragma unroll
        for (int j = 0; j < 2; j++) {
            int idx = row * 256 + j * 128 + t;      // float4 index, 0..262143
            int mat = idx >> 16;
            int off = idx & 65535;
            const float* src = (mat == 0) ? w0 : (mat == 1) ? w1
                             : (mat == 2) ? w2 : w3;
            float4 v = ((const float4*)src)[off];
            uint2 u;
            u.x = pack_h2(v.x, v.y);
            u.y = pack_h2(v.z, v.w);
            ((uint2*)wr)[(size_t)mat * 65536 + off] = u;
        }
    }

    const float4* hr = (const float4*)(h + (size_t)row * D_DIM);
    float4 x = hr[t];
    float s  = x.x + x.y + x.z + x.w;
    float ss = x.x * x.x + x.y * x.y + x.z * x.z + x.w * x.w;

    #pragma unroll
    for (int o = 16; o; o >>= 1) {
        s  += __shfl_xor_sync(0xffffffffu, s,  o);
        ss += __shfl_xor_sync(0xffffffffu, ss, o);
    }
    __shared__ float red[2][4];
    int lane = t & 31, warp = t >> 5;
    if (lane == 0) { red[0][warp] = s; red[1][warp] = ss; }
    __syncthreads();
    float a = red[0][0] + red[0][1] + red[0][2] + red[0][3];
    float c = red[1][0] + red[1][1] + red[1][2] + red[1][3];
    float mean = a * (1.0f / D_DIM);
    float var  = c * (1.0f / D_DIM) - mean * mean;
    float rstd = rsqrtf(var + 1e-5f);

    float4 wv = ((const float4*)w)[t];
    float4 bv = ((const float4*)b)[t];
    uint2 u;
    u.x = pack_h2((x.x - mean) * rstd * wv.x + bv.x,
                  (x.y - mean) * rstd * wv.y + bv.y);
    u.y = pack_h2((x.z - mean) * rstd * wv.z + bv.z,
                  (x.w - mean) * rstd * wv.w + bv.w);
    *(uint2*)(out + (size_t)row * D_DIM + t * 4) = u;
}

// ===========================================================================
// Wv transpose: wvt[j][i] = fp16(Wv[i][j])  (512x512)
// ===========================================================================
__global__ void wv_transpose(const float* __restrict__ wv, __half* __restrict__ wvt)
{
    __shared__ float tile[32][33];
    int x0 = blockIdx.x * 32;
    int y0 = blockIdx.y * 32;
    int tx = threadIdx.x & 31, ty = threadIdx.x >> 5;   // 32 x 8
    #pragma unroll
    for (int i = 0; i < 32; i += 8)
        tile[ty + i][tx] = wv[(size_t)(y0 + ty + i) * D_DIM + x0 + tx];
    __syncthreads();
    #pragma unroll
    for (int i = 0; i < 32; i += 8)
        wvt[(size_t)(x0 + ty + i) * D_DIM + y0 + tx] = __float2half_rn(tile[tx][ty + i]);
}

// ===========================================================================
// Final: out = h + sum of 4 PV partials (fp32, no intermediate rounding)
// ===========================================================================
__global__ void reduce_out(const float* __restrict__ avp,
                           const float* __restrict__ h,
                           float* __restrict__ out)
{
    int i = blockIdx.x * 256 + threadIdx.x;
    const size_t Np = (size_t)T_DIM * D_DIM / 4;
    const float4* p = (const float4*)avp;
    float4 a = p[i], b = p[i + Np], c = p[i + 2 * Np], d = p[i + 3 * Np];
    float4 hh = ((const float4*)h)[i];
    float4 o;
    o.x = hh.x + (a.x + b.x) + (c.x + d.x);
    o.y = hh.y + (a.y + b.y) + (c.y + d.y);
    o.z = hh.z + (a.z + b.z) + (c.z + d.z);
    o.w = hh.w + (a.w + b.w) + (c.w + d.w);
    ((float4*)out)[i] = o;
}

// ===========================================================================
// FP16 mma.sync GEMM (NT): C = scale*(A[M,K] @ B[N,K]^T)
// 128x128x64 block tile, 4 warps (2x2), warp 64x64, 2 CTA/SM,
// 3-stage cp.async ring, SW128 swizzle, ldmatrix, m16n8k16 fp32-acc.
//   CAUSAL:  skip blocks above diagonal; DIAGONAL blocks write NEG_BIG
//            above the row (producer-side causal mask)
//   CAPK:    cap k-loop at m0+128 (PV); reverses y-order (big CTAs first)
//   OUTH:    fp16 output; else fp32
//   KSPLIT>0: split capped k-range across blockIdx.z -> Cf + z*M*ldc
//   QKV:     blockIdx.z selects weight B+z*D*D and output {Ch,C2h,C3h};
//            z==2 writes transposed (vt, row stride ldct)
// ===========================================================================
#define BK 64
#define TILE_B (128 * 128)       // 16 KB per tile buffer
#define NSTAGE 3
#define SM_A 0
#define SM_B (NSTAGE * TILE_B)
#define SM_TOT (2 * NSTAGE * TILE_B)   // 96 KB

template<int CAUSAL, int CAPK, int OUTH, int KSPLIT, int QKV>
__global__ void __launch_bounds__(128, 2)
gemm_f16(const __half* __restrict__ A,
         const __half* __restrict__ B,
         __half* __restrict__ Ch,
         __half* __restrict__ C2h,
         __half* __restrict__ C3h,
         float* __restrict__ Cf,
         int M, int N, int K,
         int lda, int ldb, int ldc, int ldct,
         float scale)
{
    extern __shared__ char smem[];
    int yb = CAPK ? ((int)gridDim.y - 1 - (int)blockIdx.y) : (int)blockIdx.y;
    int m0 = yb * 128;
    int n0 = blockIdx.x * 128;
    if (CAUSAL && n0 > m0 + 127) return;

    const __half* Bp = B;
    __half* Chp = Ch;
    float* Cfp = Cf;
    int ldcw = ldc;
    int zq = 0;
    if (QKV) {
        zq = blockIdx.z;
        Bp = B + (size_t)zq * D_DIM * D_DIM;
        Chp = (zq == 0) ? Ch : (zq == 1) ? C2h : C3h;
        if (zq == 2) ldcw = ldct;
    }

    uint32_t sbase = smem_u32(smem);
    int t    = threadIdx.x;
    int lane = t & 31;
    int warp = t >> 5;
    int gid  = lane >> 2;
    int tig  = lane & 3;
    int wm   = (warp >> 1) * 64;
    int wn   = (warp & 1) * 64;

    int kend  = CAPK ? min(K, m0 + 128) : K;
    int iters = kend / BK;
    int it0 = 0, it1 = iters;
    if (KSPLIT > 0) {
        int z = blockIdx.z;
        it0 = (iters * z) / KSPLIT;
        it1 = (iters * (z + 1)) / KSPLIT;
        Cfp = Cf + (size_t)z * M * ldc;
    }
    int niter = it1 - it0;

    auto load_tiles = [&](int buf, int k0) {
        #pragma unroll
        for (int i = 0; i < 8; i++) {
            int f = t + i * 128;
            int row = f >> 3, kg = f & 7;
            uint32_t off = SW128((uint32_t)(row * 128 + kg * 16));
            CP_ASYNC16(sbase + SM_A + buf * TILE_B + off,
                       A + (size_t)(m0 + row) * lda + k0 + kg * 8);
        }
        #pragma unroll
        for (int i = 0; i < 8; i++) {
            int f = t + i * 128;
            int row = f >> 3, kg = f & 7;
            uint32_t off = SW128((uint32_t)(row * 128 + kg * 16));
            CP_ASYNC16(sbase + SM_B + buf * TILE_B + off,
                       Bp + (size_t)(n0 + row) * ldb + k0 + kg * 8);
        }
    };

    float acc[4][8][4];
    #pragma unroll
    for (int mi = 0; mi < 4; mi++)
        #pragma unroll
        for (int ni = 0; ni < 8; ni++)
            #pragma unroll
            for (int r = 0; r < 4; r++) acc[mi][ni][r] = 0.0f;

    int q   = lane >> 3;
    int r8  = lane & 7;
    int aq1 = (q & 1) * 8;
    int aq2 = q >> 1;
    int bq1 = (q >> 1) * 8;
    int bq2 = q & 1;

    load_tiles(0, it0 * BK);
    CP_COMMIT();
    if (niter > 1) load_tiles(1, (it0 + 1) * BK);
    CP_COMMIT();

    int buf = 0;
    for (int it = 0; it < niter; it++) {
        CP_WAIT1();
        __syncthreads();

        uint32_t sa = sbase + SM_A + buf * TILE_B;
        uint32_t sb = sbase + SM_B + buf * TILE_B;

        int nx = it + 2;
        int nbuf = buf + 2; if (nbuf >= NSTAGE) nbuf -= NSTAGE;
        if (nx < niter) load_tiles(nbuf, (it0 + nx) * BK);
        CP_COMMIT();

        #pragma unroll
        for (int ks = 0; ks < BK / 16; ks++) {
            uint32_t afr[4][4];
            #pragma unroll
            for (int mi = 0; mi < 4; mi++) {
                int row = wm + mi * 16 + aq1 + r8;
                int kg  = 2 * ks + aq2;
                uint32_t addr = sa + (uint32_t)(row * 128) + (uint32_t)((kg ^ r8) * 16);
                ldsm_x4(afr[mi][0], afr[mi][1], afr[mi][2], afr[mi][3], addr);
            }
            uint32_t bfr[8][2];
            #pragma unroll
            for (int p = 0; p < 4; p++) {
                int row = wn + p * 16 + bq1 + r8;
                int kg  = 2 * ks + bq2;
                uint32_t addr = sb + (uint32_t)(row * 128) + (uint32_t)((kg ^ r8) * 16);
                uint32_t r0, r1, r2, r3;
                ldsm_x4(r0, r1, r2, r3, addr);
                bfr[2 * p][0] = r0; bfr[2 * p][1] = r1;
                bfr[2 * p + 1][0] = r2; bfr[2 * p + 1][1] = r3;
            }
            #pragma unroll
            for (int mi = 0; mi < 4; mi++)
                #pragma unroll
                for (int ni = 0; ni < 8; ni++)
                    mma_f16(acc[mi][ni], afr[mi], bfr[ni]);
        }

        buf++; if (buf >= NSTAGE) buf = 0;
    }

    if (QKV && zq == 2) {
        // Transposed fp16 output (vt)
        __syncthreads();
        float* st = (float*)smem;        // 128 x stride 132
        #pragma unroll
        for (int mi = 0; mi < 4; mi++) {
            #pragma unroll
            for (int ni = 0; ni < 8; ni++) {
                int row = wm + mi * 16 + gid;
                int col = wn + ni * 8 + tig * 2;
                st[(col + 0) * 132 + row]     = acc[mi][ni][0];
                st[(col + 1) * 132 + row]     = acc[mi][ni][1];
                st[(col + 0) * 132 + row + 8] = acc[mi][ni][2];
                st[(col + 1) * 132 + row + 8] = acc[mi][ni][3];
            }
        }
        __syncthreads();
        #pragma unroll
        for (int i = 0; i < 16; i++) {
            int idx = t + i * 128;
            int d = idx >> 4;
            int j = idx & 15;
            const float* sp = &st[d * 132 + j * 8];
            uint4 u;
            u.x = pack_h2(sp[0], sp[1]);
            u.y = pack_h2(sp[2], sp[3]);
            u.z = pack_h2(sp[4], sp[5]);
            u.w = pack_h2(sp[6], sp[7]);
            *(uint4*)(Chp + (size_t)(n0 + d) * ldcw + m0 + j * 8) = u;
        }
        return;
    }

    if (OUTH) {
        // fp16 output; on CAUSAL diagonal blocks, mask col>row with NEG_BIG
        bool diag = CAUSAL && (n0 == m0);
        #pragma unroll
        for (int mi = 0; mi < 4; mi++) {
            #pragma unroll
            for (int ni = 0; ni < 8; ni++) {
                int row = m0 + wm + mi * 16 + gid;
                int col = n0 + wn + ni * 8 + tig * 2;
                float v00 = acc[mi][ni][0] * scale;
                float v01 = acc[mi][ni][1] * scale;
                float v10 = acc[mi][ni][2] * scale;
                float v11 = acc[mi][ni][3] * scale;
                if (diag) {
                    if (col > row)         v00 = NEG_BIG;
                    if (col + 1 > row)     v01 = NEG_BIG;
                    if (col > row + 8)     v10 = NEG_BIG;
                    if (col + 1 > row + 8) v11 = NEG_BIG;
                }
                *(uint32_t*)(Chp + (size_t)row * ldcw + col)       = pack_h2(v00, v01);
                *(uint32_t*)(Chp + (size_t)(row + 8) * ldcw + col) = pack_h2(v10, v11);
            }
        }
        return;
    }

    // fp32 output (PV partials, raw)
    #pragma unroll
    for (int mi = 0; mi < 4; mi++) {
        #pragma unroll
        for (int ni = 0; ni < 8; ni++) {
            int row = m0 + wm + mi * 16 + gid;
            int col = n0 + wn + ni * 8 + tig * 2;
            float2 o0, o1;
            o0.x = acc[mi][ni][0]; o0.y = acc[mi][ni][1];
            o1.x = acc[mi][ni][2]; o1.y = acc[mi][ni][3];
            *(float2*)(Cfp + (size_t)row * ldcw + col) = o0;
            *(float2*)(Cfp + (size_t)(row + 8) * ldcw + col) = o1;
        }
    }
}

// ===========================================================================
// Causal row softmax over fp16 S (in place). Producer wrote NEG_BIG above
// the diagonal, so NO per-element causal compares: per-thread 8-element
// groups are either fully active (j0 < zend) or substituted with NEG_BIG.
// exp(NEG_BIG - mx) == 0, so masked entries become exact zeros.
// ===========================================================================
__device__ __forceinline__ float block_reduce(float v, bool is_max)
{
    __shared__ float sm[8];
    __syncthreads();
    #pragma unroll
    for (int o = 16; o; o >>= 1) {
        float u = __shfl_xor_sync(0xffffffffu, v, o);
        v = is_max ? fmaxf(v, u) : (v + u);
    }
    int lane = threadIdx.x & 31, warp = threadIdx.x >> 5;
    if (lane == 0) sm[warp] = v;
    __syncthreads();
    float r = sm[0];
    #pragma unroll
    for (int i = 1; i < 8; i++)
        r = is_max ? fmaxf(r, sm[i]) : (r + sm[i]);
    return r;
}

__global__ void softmax_causal(__half* __restrict__ S)
{
    int row = blockIdx.x;
    int t = threadIdx.x;                 // 0..255
    int zend = (row & ~127) + 128;       // zero-pad cap (= PV k-cap)
    uint4* Srow = (uint4*)(S + (size_t)row * T_DIM);   // 8 halves per uint4

    float x[4][8];
    float mx = -INFINITY;
    #pragma unroll
    for (int it = 0; it < 4; it++) {
        int j0 = (it << 11) + t * 8;
        bool grp = (j0 < zend);          // group-uniform (zend % 128 == 0)
        uint4 u = make_uint4(0, 0, 0, 0);
        if (grp) u = Srow[(it << 8) + t];
        float2 f0 = __half22float2(*(__half2*)&u.x);
        float2 f1 = __half22float2(*(__half2*)&u.y);
        float2 f2 = __half22float2(*(__half2*)&u.z);
        float2 f3 = __half22float2(*(__half2*)&u.w);
        x[it][0] = grp ? f0.x : NEG_BIG; x[it][1] = grp ? f0.y : NEG_BIG;
        x[it][2] = grp ? f1.x : NEG_BIG; x[it][3] = grp ? f1.y : NEG_BIG;
        x[it][4] = grp ? f2.x : NEG_BIG; x[it][5] = grp ? f2.y : NEG_BIG;
        x[it][6] = grp ? f3.x : NEG_BIG; x[it][7] = grp ? f3.y : NEG_BIG;
        #pragma unroll
        for (int e = 0; e < 8; e++) mx = fmaxf(mx, x[it][e]);
    }
    mx = block_reduce(mx, true);

    float sum = 0.0f;
    #pragma unroll
    for (int it = 0; it < 4; it++) {
        #pragma unroll
        for (int e = 0; e < 8; e++) {
            x[it][e] = __expf(x[it][e] - mx);
            sum += x[it][e];
        }
    }
    sum = block_reduce(sum, false);
    float inv = 1.0f / sum;

    #pragma unroll
    for (int it = 0; it < 4; it++) {
        int j0 = (it << 11) + t * 8;
        if (j0 < zend) {
            uint4 u;
            u.x = pack_h2(x[it][0] * inv, x[it][1] * inv);
            u.y = pack_h2(x[it][2] * inv, x[it][3] * inv);
            u.z = pack_h2(x[it][4] * inv, x[it][5] * inv);
            u.w = pack_h2(x[it][6] * inv, x[it][7] * inv);
            Srow[(it << 8) + t] = u;
        }
    }
}

// ===========================================================================
extern "C" void kernel_launch(void* const* d_in, const int* in_sizes, int n_in,
                              void* d_out, int out_size)
{
    const float* h    = (const float*)d_in[0];
    const float* ln_w = (const float*)d_in[1];
    const float* ln_b = (const float*)d_in[2];
    const float* w_q  = (const float*)d_in[3];
    const float* w_k  = (const float*)d_in[4];
    const float* w_v  = (const float*)d_in[5];
    const float* w_o  = (const float*)d_in[6];
    float* out = (float*)d_out;

    __half *hn, *q, *k, *vt, *S, *wr, *wvt;
    float *avp;
    cudaGetSymbolAddress((void**)&hn,  g_hnorm);
    cudaGetSymbolAddress((void**)&q,   g_q);
    cudaGetSymbolAddress((void**)&k,   g_k);
    cudaGetSymbolAddress((void**)&vt,  g_vt);
    cudaGetSymbolAddress((void**)&avp, g_avp);
    cudaGetSymbolAddress((void**)&S,   g_S);
    cudaGetSymbolAddress((void**)&wr,  g_wr);
    cudaGetSymbolAddress((void**)&wvt, g_wvt);
    __half* wp_r = wr + 2 * (size_t)D_DIM * D_DIM;   // W' slot
    __half* wo_r = wr + 3 * (size_t)D_DIM * D_DIM;   // Wo slot

    cudaFuncSetAttribute((const void*)gemm_f16<0,0,1,0,1>,
                         cudaFuncAttributeMaxDynamicSharedMemorySize, SM_TOT);
    cudaFuncSetAttribute((const void*)gemm_f16<1,0,1,0,0>,
                         cudaFuncAttributeMaxDynamicSharedMemorySize, SM_TOT);
    cudaFuncSetAttribute((const void*)gemm_f16<0,1,0,4,0>,
                         cudaFuncAttributeMaxDynamicSharedMemorySize, SM_TOT);
    cudaFuncSetAttribute((const void*)gemm_f16<0,0,1,0,0>,
                         cudaFuncAttributeMaxDynamicSharedMemorySize, SM_TOT);

    const float inv_sqrt_d = 0.044194173824159216f;  // 1/sqrt(512)

    // 1) LayerNorm -> fp16 (+ fused fp16 weight rounding into g_wr)
    ln_kernel<<<T_DIM, 128>>>(h, ln_w, ln_b, hn, w_q, w_k, w_v, w_o, wr);

    // 1b) Wv^T (fp16)
    dim3 gT(D_DIM / 32, D_DIM / 32);   // (16, 16)
    wv_transpose<<<gT, 256>>>(w_v, wvt);

    // 1c) W' = Wo @ Wv  (NT: A = Wo fp16, B = Wv^T fp16) -> g_wr slot 2
    dim3 gWp(D_DIM / 128, D_DIM / 128);  // (4, 4)
    gemm_f16<0,0,1,0,0><<<gWp, 128, SM_TOT>>>(wo_r, wvt,
        wp_r, nullptr, nullptr, nullptr,
        D_DIM, D_DIM, D_DIM, D_DIM, D_DIM, D_DIM, 0, 1.0f);

    // 2) Q, K, V' in ONE launch (z=2 uses W', writes V'^T transposed)
    dim3 gQKV(D_DIM / 128, T_DIM / 128, 3);  // (4, 64, 3)
    gemm_f16<0,0,1,0,1><<<gQKV, 128, SM_TOT>>>(hn, wr,
        q, k, vt, nullptr,
        T_DIM, D_DIM, D_DIM, D_DIM, D_DIM, D_DIM, T_DIM, 1.0f);

    // 3) Scores = Q @ K^T * 1/sqrt(d) -> fp16 S; diagonal blocks pre-masked
    dim3 gScore(T_DIM / 128, T_DIM / 128);  // (64, 64)
    gemm_f16<1,0,1,0,0><<<gScore, 128, SM_TOT>>>(q, k,
        S, nullptr, nullptr, nullptr,
        T_DIM, T_DIM, D_DIM, D_DIM, D_DIM, T_DIM, 0, inv_sqrt_d);

    // 4) Causal softmax (mask-free hot path)
    softmax_causal<<<T_DIM, 256>>>(S);

    // 5) AV' partials = softmax(S) @ V'^T (k-capped, split-K4, fp32 partials)
    dim3 gPV(D_DIM / 128, T_DIM / 128, 4);  // (4, 64, 4)
    gemm_f16<0,1,0,4,0><<<gPV, 128, SM_TOT>>>(S, vt,
        nullptr, nullptr, nullptr, avp,
        T_DIM, D_DIM, T_DIM, T_DIM, T_DIM, D_DIM, 0, 1.0f);

    // 6) out = h + sum of 4 partials (pure fp32 elementwise)
    reduce_out<<<(T_DIM * D_DIM) / 4 / 256, 256>>>(avp, h, out);
}

// round 14
// speedup vs baseline: 1.9059x; 1.0002x over previous
#include <cuda_runtime.h>
#include <cuda_fp16.h>
#include <math.h>
#include <stdint.h>

#define T_DIM 8192
#define D_DIM 512

// Scratch (allocation-free rule: __device__ globals)
__device__ __half g_hnorm[T_DIM * D_DIM];
__device__ __half g_q[T_DIM * D_DIM];
__device__ __half g_k[T_DIM * D_DIM];
__device__ __half g_vt[T_DIM * D_DIM];            // V'^T : [d][T], V' = hn @ (Wo Wv)^T
__device__ float  g_avp[4][T_DIM * D_DIM];        // PV split-K partials (fp32)
__device__ __half g_wr[4][D_DIM * D_DIM];         // fp16 weights: q, k, (W'), o
__device__ __half g_wvt[D_DIM * D_DIM];           // Wv^T fp16
__device__ __half g_S[(size_t)T_DIM * T_DIM];     // 128 MB score/prob matrix

// ===========================================================================
// Helpers
// ===========================================================================
__device__ __forceinline__ uint32_t smem_u32(const void* p) {
    uint32_t a;
    asm("{ .reg .u64 t; cvta.to.shared.u64 t, %1; cvt.u32.u64 %0, t; }" : "=r"(a) : "l"(p));
    return a;
}
__device__ __forceinline__ uint32_t pack_h2(float a, float b) {
    __half2 h = __floats2half2_rn(a, b);
    return *(uint32_t*)&h;
}
#define SW128(o) ((o) ^ ((((uint32_t)(o)) >> 3) & 0x70))
#define NEG_BIG (-60000.0f)
#define SM_SHIFT 20.0f          // uniform softmax shift (scores bounded << 88-20)

#define CP_ASYNC16(dst, src) \
    asm volatile("cp.async.cg.shared.global [%0], [%1], 16;" :: "r"(dst), "l"(src) : "memory")
#define CP_COMMIT() asm volatile("cp.async.commit_group;" ::: "memory")
#define CP_WAIT1()  asm volatile("cp.async.wait_group 1;" ::: "memory")

__device__ __forceinline__ void ldsm_x4(uint32_t& r0, uint32_t& r1, uint32_t& r2, uint32_t& r3,
                                        uint32_t addr) {
    asm volatile("ldmatrix.sync.aligned.m8n8.x4.shared.b16 {%0,%1,%2,%3}, [%4];"
                 : "=r"(r0), "=r"(r1), "=r"(r2), "=r"(r3) : "r"(addr));
}

// fp16 MMA, fp32 accumulate: m16n8k16
__device__ __forceinline__ void mma_f16(float* c, const uint32_t* a, const uint32_t* b) {
    asm volatile(
        "mma.sync.aligned.m16n8k16.row.col.f32.f16.f16.f32 "
        "{%0,%1,%2,%3}, {%4,%5,%6,%7}, {%8,%9}, {%0,%1,%2,%3};"
        : "+f"(c[0]), "+f"(c[1]), "+f"(c[2]), "+f"(c[3])
        : "r"(a[0]), "r"(a[1]), "r"(a[2]), "r"(a[3]),
          "r"(b[0]), "r"(b[1]));
}

// ===========================================================================
// LayerNorm (one block/row, 128 thr) -> fp16 output.
// Blocks 0..1023 additionally round the 4 weight matrices into g_wr (fp16).
// ===========================================================================
__global__ void ln_kernel(const float* __restrict__ h,
                          const float* __restrict__ w,
                          const float* __restrict__ b,
                          __half* __restrict__ out,
                          const float* __restrict__ w0,
                          const float* __restrict__ w1,
                          const float* __restrict__ w2,
                          const float* __restrict__ w3,
                          __half* __restrict__ wr)
{
    int row = blockIdx.x;
    int t = threadIdx.x;

    if (row < 1024) {
        #pragma unroll
        for (int j = 0; j < 2; j++) {
            int idx = row * 256 + j * 128 + t;      // float4 index, 0..262143
            int mat = idx >> 16;
            int off = idx & 65535;
            const float* src = (mat == 0) ? w0 : (mat == 1) ? w1
                             : (mat == 2) ? w2 : w3;
            float4 v = ((const float4*)src)[off];
            uint2 u;
            u.x = pack_h2(v.x, v.y);
            u.y = pack_h2(v.z, v.w);
            ((uint2*)wr)[(size_t)mat * 65536 + off] = u;
        }
    }

    const float4* hr = (const float4*)(h + (size_t)row * D_DIM);
    float4 x = hr[t];
    float s  = x.x + x.y + x.z + x.w;
    float ss = x.x * x.x + x.y * x.y + x.z * x.z + x.w * x.w;

    #pragma unroll
    for (int o = 16; o; o >>= 1) {
        s  += __shfl_xor_sync(0xffffffffu, s,  o);
        ss += __shfl_xor_sync(0xffffffffu, ss, o);
    }
    __shared__ float red[2][4];
    int lane = t & 31, warp = t >> 5;
    if (lane == 0) { red[0][warp] = s; red[1][warp] = ss; }
    __syncthreads();
    float a = red[0][0] + red[0][1] + red[0][2] + red[0][3];
    float c = red[1][0] + red[1][1] + red[1][2] + red[1][3];
    float mean = a * (1.0f / D_DIM);
    float var  = c * (1.0f / D_DIM) - mean * mean;
    float rstd = rsqrtf(var + 1e-5f);

    float4 wv = ((const float4*)w)[t];
    float4 bv = ((const float4*)b)[t];
    uint2 u;
    u.x = pack_h2((x.x - mean) * rstd * wv.x + bv.x,
                  (x.y - mean) * rstd * wv.y + bv.y);
    u.y = pack_h2((x.z - mean) * rstd * wv.z + bv.z,
                  (x.w - mean) * rstd * wv.w + bv.w);
    *(uint2*)(out + (size_t)row * D_DIM + t * 4) = u;
}

// ===========================================================================
// Wv transpose: wvt[j][i] = fp16(Wv[i][j])  (512x512)
// ===========================================================================
__global__ void wv_transpose(const float* __restrict__ wv, __half* __restrict__ wvt)
{
    __shared__ float tile[32][33];
    int x0 = blockIdx.x * 32;
    int y0 = blockIdx.y * 32;
    int tx = threadIdx.x & 31, ty = threadIdx.x >> 5;   // 32 x 8
    #pragma unroll
    for (int i = 0; i < 32; i += 8)
        tile[ty + i][tx] = wv[(size_t)(y0 + ty + i) * D_DIM + x0 + tx];
    __syncthreads();
    #pragma unroll
    for (int i = 0; i < 32; i += 8)
        wvt[(size_t)(x0 + ty + i) * D_DIM + y0 + tx] = __float2half_rn(tile[tx][ty + i]);
}

// ===========================================================================
// Final: out = sum of 4 PV partials (z=0 partial already contains +h)
// ===========================================================================
__global__ void reduce_out(const float* __restrict__ avp,
                           float* __restrict__ out)
{
    int i = blockIdx.x * 256 + threadIdx.x;
    const size_t Np = (size_t)T_DIM * D_DIM / 4;
    const float4* p = (const float4*)avp;
    float4 a = p[i], b = p[i + Np], c = p[i + 2 * Np], d = p[i + 3 * Np];
    float4 o;
    o.x = (a.x + b.x) + (c.x + d.x);
    o.y = (a.y + b.y) + (c.y + d.y);
    o.z = (a.z + b.z) + (c.z + d.z);
    o.w = (a.w + b.w) + (c.w + d.w);
    ((float4*)out)[i] = o;
}

// ===========================================================================
// FP16 mma.sync GEMM (NT): C = scale*(A[M,K] @ B[N,K]^T)
// 128x128x64 block tile, 4 warps (2x2), warp 64x64, 2 CTA/SM,
// 3-stage cp.async ring, SW128 swizzle, ldmatrix, m16n8k16 fp32-acc.
//   CAUSAL:  skip blocks above diagonal; DIAGONAL blocks write NEG_BIG
//   CAPK:    cap k-loop at m0+128 (PV); reverses y-order (big CTAs first)
//   OUTH:    fp16 output; else fp32
//   KSPLIT>0: split capped k-range across blockIdx.z -> Cf + z*M*ldc;
//            z==0 partial adds residual res (if non-null)
//   QKV:     blockIdx.z selects weight B+z*D*D and output {Ch,C2h,C3h};
//            z==0 applies scale (Q/sqrt(d)); z==2 writes transposed (vt)
// ===========================================================================
#define BK 64
#define TILE_B (128 * 128)       // 16 KB per tile buffer
#define NSTAGE 3
#define SM_A 0
#define SM_B (NSTAGE * TILE_B)
#define SM_TOT (2 * NSTAGE * TILE_B)   // 96 KB

template<int CAUSAL, int CAPK, int OUTH, int KSPLIT, int QKV>
__global__ void __launch_bounds__(128, 2)
gemm_f16(const __half* __restrict__ A,
         const __half* __restrict__ B,
         __half* __restrict__ Ch,
         __half* __restrict__ C2h,
         __half* __restrict__ C3h,
         float* __restrict__ Cf,
         const float* __restrict__ res,
         int M, int N, int K,
         int lda, int ldb, int ldc, int ldct,
         float scale)
{
    extern __shared__ char smem[];
    int yb = CAPK ? ((int)gridDim.y - 1 - (int)blockIdx.y) : (int)blockIdx.y;
    int m0 = yb * 128;
    int n0 = blockIdx.x * 128;
    if (CAUSAL && n0 > m0 + 127) return;

    const __half* Bp = B;
    __half* Chp = Ch;
    float* Cfp = Cf;
    int ldcw = ldc;
    int zq = 0;
    float sc = scale;
    if (QKV) {
        zq = blockIdx.z;
        Bp = B + (size_t)zq * D_DIM * D_DIM;
        Chp = (zq == 0) ? Ch : (zq == 1) ? C2h : C3h;
        if (zq == 2) ldcw = ldct;
        if (zq != 0) sc = 1.0f;       // scale only applies to Q
    }

    uint32_t sbase = smem_u32(smem);
    int t    = threadIdx.x;
    int lane = t & 31;
    int warp = t >> 5;
    int gid  = lane >> 2;
    int tig  = lane & 3;
    int wm   = (warp >> 1) * 64;
    int wn   = (warp & 1) * 64;

    int kend  = CAPK ? min(K, m0 + 128) : K;
    int iters = kend / BK;
    int it0 = 0, it1 = iters;
    if (KSPLIT > 0) {
        int z = blockIdx.z;
        it0 = (iters * z) / KSPLIT;
        it1 = (iters * (z + 1)) / KSPLIT;
        Cfp = Cf + (size_t)z * M * ldc;
    }
    int niter = it1 - it0;

    auto load_tiles = [&](int buf, int k0) {
        #pragma unroll
        for (int i = 0; i < 8; i++) {
            int f = t + i * 128;
            int row = f >> 3, kg = f & 7;
            uint32_t off = SW128((uint32_t)(row * 128 + kg * 16));
            CP_ASYNC16(sbase + SM_A + buf * TILE_B + off,
                       A + (size_t)(m0 + row) * lda + k0 + kg * 8);
        }
        #pragma unroll
        for (int i = 0; i < 8; i++) {
            int f = t + i * 128;
            int row = f >> 3, kg = f & 7;
            uint32_t off = SW128((uint32_t)(row * 128 + kg * 16));
            CP_ASYNC16(sbase + SM_B + buf * TILE_B + off,
                       Bp + (size_t)(n0 + row) * ldb + k0 + kg * 8);
        }
    };

    float acc[4][8][4];
    #pragma unroll
    for (int mi = 0; mi < 4; mi++)
        #pragma unroll
        for (int ni = 0; ni < 8; ni++)
            #pragma unroll
            for (int r = 0; r < 4; r++) acc[mi][ni][r] = 0.0f;

    int q   = lane >> 3;
    int r8  = lane & 7;
    int aq1 = (q & 1) * 8;
    int aq2 = q >> 1;
    int bq1 = (q >> 1) * 8;
    int bq2 = q & 1;

    load_tiles(0, it0 * BK);
    CP_COMMIT();
    if (niter > 1) load_tiles(1, (it0 + 1) * BK);
    CP_COMMIT();

    int buf = 0;
    for (int it = 0; it < niter; it++) {
        CP_WAIT1();
        __syncthreads();

        uint32_t sa = sbase + SM_A + buf * TILE_B;
        uint32_t sb = sbase + SM_B + buf * TILE_B;

        int nx = it + 2;
        int nbuf = buf + 2; if (nbuf >= NSTAGE) nbuf -= NSTAGE;
        if (nx < niter) load_tiles(nbuf, (it0 + nx) * BK);
        CP_COMMIT();

        #pragma unroll
        for (int ks = 0; ks < BK / 16; ks++) {
            uint32_t afr[4][4];
            #pragma unroll
            for (int mi = 0; mi < 4; mi++) {
                int row = wm + mi * 16 + aq1 + r8;
                int kg  = 2 * ks + aq2;
                uint32_t addr = sa + (uint32_t)(row * 128) + (uint32_t)((kg ^ r8) * 16);
                ldsm_x4(afr[mi][0], afr[mi][1], afr[mi][2], afr[mi][3], addr);
            }
            uint32_t bfr[8][2];
            #pragma unroll
            for (int p = 0; p < 4; p++) {
                int row = wn + p * 16 + bq1 + r8;
                int kg  = 2 * ks + bq2;
                uint32_t addr = sb + (uint32_t)(row * 128) + (uint32_t)((kg ^ r8) * 16);
                uint32_t r0, r1, r2, r3;
                ldsm_x4(r0, r1, r2, r3, addr);
                bfr[2 * p][0] = r0; bfr[2 * p][1] = r1;
                bfr[2 * p + 1][0] = r2; bfr[2 * p + 1][1] = r3;
            }
            #pragma unroll
            for (int mi = 0; mi < 4; mi++)
                #pragma unroll
                for (int ni = 0; ni < 8; ni++)
                    mma_f16(acc[mi][ni], afr[mi], bfr[ni]);
        }

        buf++; if (buf >= NSTAGE) buf = 0;
    }

    if (QKV && zq == 2) {
        // Transposed fp16 output (vt)
        __syncthreads();
        float* st = (float*)smem;        // 128 x stride 132
        #pragma unroll
        for (int mi = 0; mi < 4; mi++) {
            #pragma unroll
            for (int ni = 0; ni < 8; ni++) {
                int row = wm + mi * 16 + gid;
                int col = wn + ni * 8 + tig * 2;
                st[(col + 0) * 132 + row]     = acc[mi][ni][0];
                st[(col + 1) * 132 + row]     = acc[mi][ni][1];
                st[(col + 0) * 132 + row + 8] = acc[mi][ni][2];
                st[(col + 1) * 132 + row + 8] = acc[mi][ni][3];
            }
        }
        __syncthreads();
        #pragma unroll
        for (int i = 0; i < 16; i++) {
            int idx = t + i * 128;
            int d = idx >> 4;
            int j = idx & 15;
            const float* sp = &st[d * 132 + j * 8];
            uint4 u;
            u.x = pack_h2(sp[0], sp[1]);
            u.y = pack_h2(sp[2], sp[3]);
            u.z = pack_h2(sp[4], sp[5]);
            u.w = pack_h2(sp[6], sp[7]);
            *(uint4*)(Chp + (size_t)(n0 + d) * ldcw + m0 + j * 8) = u;
        }
        return;
    }

    if (OUTH) {
        // fp16 output; on CAUSAL diagonal blocks, mask col>row with NEG_BIG
        bool diag = CAUSAL && (n0 == m0);
        #pragma unroll
        for (int mi = 0; mi < 4; mi++) {
            #pragma unroll
            for (int ni = 0; ni < 8; ni++) {
                int row = m0 + wm + mi * 16 + gid;
                int col = n0 + wn + ni * 8 + tig * 2;
                float v00 = acc[mi][ni][0] * sc;
                float v01 = acc[mi][ni][1] * sc;
                float v10 = acc[mi][ni][2] * sc;
                float v11 = acc[mi][ni][3] * sc;
                if (diag) {
                    if (col > row)         v00 = NEG_BIG;
                    if (col + 1 > row)     v01 = NEG_BIG;
                    if (col > row + 8)     v10 = NEG_BIG;
                    if (col + 1 > row + 8) v11 = NEG_BIG;
                }
                *(uint32_t*)(Chp + (size_t)row * ldcw + col)       = pack_h2(v00, v01);
                *(uint32_t*)(Chp + (size_t)(row + 8) * ldcw + col) = pack_h2(v10, v11);
            }
        }
        return;
    }

    // fp32 output (PV partials, raw; z=0 adds residual)
    bool addres = (KSPLIT > 0) && (blockIdx.z == 0) && (res != nullptr);
    #pragma unroll
    for (int mi = 0; mi < 4; mi++) {
        #pragma unroll
        for (int ni = 0; ni < 8; ni++) {
            int row = m0 + wm + mi * 16 + gid;
            int col = n0 + wn + ni * 8 + tig * 2;
            float2 o0, o1;
            o0.x = acc[mi][ni][0]; o0.y = acc[mi][ni][1];
            o1.x = acc[mi][ni][2]; o1.y = acc[mi][ni][3];
            size_t i0 = (size_t)row * ldcw + col;
            size_t i1 = (size_t)(row + 8) * ldcw + col;
            if (addres) {
                float2 r0 = *(const float2*)(res + i0);
                float2 r1 = *(const float2*)(res + i1);
                o0.x += r0.x; o0.y += r0.y;
                o1.x += r1.x; o1.y += r1.y;
            }
            *(float2*)(Cfp + i0) = o0;
            *(float2*)(Cfp + i1) = o1;
        }
    }
}

// ===========================================================================
// Causal row softmax over fp16 S (in place), SINGLE PASS:
// softmax(s) = exp(s - C) / sum(exp(s - C)) for any constant C; scores here
// are bounded |s| << 68, so C = SM_SHIFT avoids overflow without a row-max
// pass. Masked entries are NEG_BIG -> exp underflows to exact 0.
// Per-thread 8-element groups are group-uniform active (zend % 128 == 0).
// ===========================================================================
__device__ __forceinline__ float block_reduce_sum(float v)
{
    __shared__ float sm[8];
    #pragma unroll
    for (int o = 16; o; o >>= 1)
        v += __shfl_xor_sync(0xffffffffu, v, o);
    int lane = threadIdx.x & 31, warp = threadIdx.x >> 5;
    if (lane == 0) sm[warp] = v;
    __syncthreads();
    float r = sm[0];
    #pragma unroll
    for (int i = 1; i < 8; i++) r += sm[i];
    return r;
}

__global__ void softmax_causal(__half* __restrict__ S)
{
    int row = blockIdx.x;
    int t = threadIdx.x;                 // 0..255
    int zend = (row & ~127) + 128;       // zero-pad cap (= PV k-cap)
    uint4* Srow = (uint4*)(S + (size_t)row * T_DIM);   // 8 halves per uint4

    float x[4][8];
    float sum = 0.0f;
    #pragma unroll
    for (int it = 0; it < 4; it++) {
        int j0 = (it << 11) + t * 8;
        bool grp = (j0 < zend);          // group-uniform
        uint4 u = make_uint4(0, 0, 0, 0);
        if (grp) u = Srow[(it << 8) + t];
        float2 f0 = __half22float2(*(__half2*)&u.x);
        float2 f1 = __half22float2(*(__half2*)&u.y);
        float2 f2 = __half22float2(*(__half2*)&u.z);
        float2 f3 = __half22float2(*(__half2*)&u.w);
        float g = grp ? 0.0f : 1.0f;
        x[it][0] = __expf((grp ? f0.x : NEG_BIG) - SM_SHIFT);
        x[it][1] = __expf((grp ? f0.y : NEG_BIG) - SM_SHIFT);
        x[it][2] = __expf((grp ? f1.x : NEG_BIG) - SM_SHIFT);
        x[it][3] = __expf((grp ? f1.y : NEG_BIG) - SM_SHIFT);
        x[it][4] = __expf((grp ? f2.x : NEG_BIG) - SM_SHIFT);
        x[it][5] = __expf((grp ? f2.y : NEG_BIG) - SM_SHIFT);
        x[it][6] = __expf((grp ? f3.x : NEG_BIG) - SM_SHIFT);
        x[it][7] = __expf((grp ? f3.y : NEG_BIG) - SM_SHIFT);
        (void)g;
        #pragma unroll
        for (int e = 0; e < 8; e++) sum += x[it][e];
    }
    sum = block_reduce_sum(sum);
    float inv = 1.0f / sum;

    #pragma unroll
    for (int it = 0; it < 4; it++) {
        int j0 = (it << 11) + t * 8;
        if (j0 < zend) {
            uint4 u;
            u.x = pack_h2(x[it][0] * inv, x[it][1] * inv);
            u.y = pack_h2(x[it][2] * inv, x[it][3] * inv);
            u.z = pack_h2(x[it][4] * inv, x[it][5] * inv);
            u.w = pack_h2(x[it][6] * inv, x[it][7] * inv);
            Srow[(it << 8) + t] = u;
        }
    }
}

// ===========================================================================
extern "C" void kernel_launch(void* const* d_in, const int* in_sizes, int n_in,
                              void* d_out, int out_size)
{
    const float* h    = (const float*)d_in[0];
    const float* ln_w = (const float*)d_in[1];
    const float* ln_b = (const float*)d_in[2];
    const float* w_q  = (const float*)d_in[3];
    const float* w_k  = (const float*)d_in[4];
    const float* w_v  = (const float*)d_in[5];
    const float* w_o  = (const float*)d_in[6];
    float* out = (float*)d_out;

    __half *hn, *q, *k, *vt, *S, *wr, *wvt;
    float *avp;
    cudaGetSymbolAddress((void**)&hn,  g_hnorm);
    cudaGetSymbolAddress((void**)&q,   g_q);
    cudaGetSymbolAddress((void**)&k,   g_k);
    cudaGetSymbolAddress((void**)&vt,  g_vt);
    cudaGetSymbolAddress((void**)&avp, g_avp);
    cudaGetSymbolAddress((void**)&S,   g_S);
    cudaGetSymbolAddress((void**)&wr,  g_wr);
    cudaGetSymbolAddress((void**)&wvt, g_wvt);
    __half* wp_r = wr + 2 * (size_t)D_DIM * D_DIM;   // W' slot
    __half* wo_r = wr + 3 * (size_t)D_DIM * D_DIM;   // Wo slot

    cudaFuncSetAttribute((const void*)gemm_f16<0,0,1,0,1>,
                         cudaFuncAttributeMaxDynamicSharedMemorySize, SM_TOT);
    cudaFuncSetAttribute((const void*)gemm_f16<1,0,1,0,0>,
                         cudaFuncAttributeMaxDynamicSharedMemorySize, SM_TOT);
    cudaFuncSetAttribute((const void*)gemm_f16<0,1,0,4,0>,
                         cudaFuncAttributeMaxDynamicSharedMemorySize, SM_TOT);
    cudaFuncSetAttribute((const void*)gemm_f16<0,0,1,0,0>,
                         cudaFuncAttributeMaxDynamicSharedMemorySize, SM_TOT);

    const float inv_sqrt_d = 0.044194173824159216f;  // 1/sqrt(512)

    // 1) LayerNorm -> fp16 (+ fused fp16 weight rounding into g_wr)
    ln_kernel<<<T_DIM, 128>>>(h, ln_w, ln_b, hn, w_q, w_k, w_v, w_o, wr);

    // 1b) Wv^T (fp16)
    dim3 gT(D_DIM / 32, D_DIM / 32);   // (16, 16)
    wv_transpose<<<gT, 256>>>(w_v, wvt);

    // 1c) W' = Wo @ Wv  (NT) -> g_wr slot 2
    dim3 gWp(D_DIM / 128, D_DIM / 128);  // (4, 4)
    gemm_f16<0,0,1,0,0><<<gWp, 128, SM_TOT>>>(wo_r, wvt,
        wp_r, nullptr, nullptr, nullptr, nullptr,
        D_DIM, D_DIM, D_DIM, D_DIM, D_DIM, D_DIM, 0, 1.0f);

    // 2) Q (pre-scaled by 1/sqrt(d)), K, V' in ONE launch
    dim3 gQKV(D_DIM / 128, T_DIM / 128, 3);  // (4, 64, 3)
    gemm_f16<0,0,1,0,1><<<gQKV, 128, SM_TOT>>>(hn, wr,
        q, k, vt, nullptr, nullptr,
        T_DIM, D_DIM, D_DIM, D_DIM, D_DIM, D_DIM, T_DIM, inv_sqrt_d);

    // 3) Scores = Q @ K^T -> fp16 S; diagonal blocks pre-masked (scale=1)
    dim3 gScore(T_DIM / 128, T_DIM / 128);  // (64, 64)
    gemm_f16<1,0,1,0,0><<<gScore, 128, SM_TOT>>>(q, k,
        S, nullptr, nullptr, nullptr, nullptr,
        T_DIM, T_DIM, D_DIM, D_DIM, D_DIM, T_DIM, 0, 1.0f);

    // 4) Causal softmax (single pass, constant shift)
    softmax_causal<<<T_DIM, 256>>>(S);

    // 5) AV' partials = softmax(S) @ V'^T (k-capped, split-K4; z=0 adds h)
    dim3 gPV(D_DIM / 128, T_DIM / 128, 4);  // (4, 64, 4)
    gemm_f16<0,1,0,4,0><<<gPV, 128, SM_TOT>>>(S, vt,
        nullptr, nullptr, nullptr, avp, h,
        T_DIM, D_DIM, T_DIM, T_DIM, T_DIM, D_DIM, 0, 1.0f);

    // 6) out = sum of 4 partials (h already inside z=0 partial)
    reduce_out<<<(T_DIM * D_DIM) / 4 / 256, 256>>>(avp, out);
}

// round 15
// speedup vs baseline: 2.0291x; 1.0646x over previous
#include <cuda_runtime.h>
#include <cuda_fp16.h>
#include <math.h>
#include <stdint.h>

#define T_DIM 8192
#define D_DIM 512

// Scratch (allocation-free rule: __device__ globals)
__device__ __half g_hnorm[T_DIM * D_DIM];
__device__ __half g_q[T_DIM * D_DIM];
__device__ __half g_k[T_DIM * D_DIM];
__device__ __half g_vt[T_DIM * D_DIM];            // V'^T : [d][T], V' = hn @ (Wo Wv)^T
__device__ float  g_avp[4][T_DIM * D_DIM];        // PV split-K partials (fp32)
__device__ __half g_wr[4][D_DIM * D_DIM];         // fp16 weights: q, k, (W'), o
__device__ __half g_wvt[D_DIM * D_DIM];           // Wv^T fp16
__device__ __half g_S[(size_t)T_DIM * T_DIM];     // 128 MB score/prob matrix

// ===========================================================================
// Helpers
// ===========================================================================
__device__ __forceinline__ uint32_t smem_u32(const void* p) {
    uint32_t a;
    asm("{ .reg .u64 t; cvta.to.shared.u64 t, %1; cvt.u32.u64 %0, t; }" : "=r"(a) : "l"(p));
    return a;
}
__device__ __forceinline__ uint32_t pack_h2(float a, float b) {
    __half2 h = __floats2half2_rn(a, b);
    return *(uint32_t*)&h;
}
#define SW128(o) ((o) ^ ((((uint32_t)(o)) >> 3) & 0x70))
#define NEG_BIG (-60000.0f)
#define SM_SHIFT 20.0f          // uniform softmax shift (scores bounded << 88-20)

#define CP_ASYNC16(dst, src) \
    asm volatile("cp.async.cg.shared.global [%0], [%1], 16;" :: "r"(dst), "l"(src) : "memory")
#define CP_COMMIT() asm volatile("cp.async.commit_group;" ::: "memory")
#define CP_WAIT1()  asm volatile("cp.async.wait_group 1;" ::: "memory")

__device__ __forceinline__ void ldsm_x4(uint32_t& r0, uint32_t& r1, uint32_t& r2, uint32_t& r3,
                                        uint32_t addr) {
    asm volatile("ldmatrix.sync.aligned.m8n8.x4.shared.b16 {%0,%1,%2,%3}, [%4];"
                 : "=r"(r0), "=r"(r1), "=r"(r2), "=r"(r3) : "r"(addr));
}

// fp16 MMA, fp32 accumulate: m16n8k16
__device__ __forceinline__ void mma_f16(float* c, const uint32_t* a, const uint32_t* b) {
    asm volatile(
        "mma.sync.aligned.m16n8k16.row.col.f32.f16.f16.f32 "
        "{%0,%1,%2,%3}, {%4,%5,%6,%7}, {%8,%9}, {%0,%1,%2,%3};"
        : "+f"(c[0]), "+f"(c[1]), "+f"(c[2]), "+f"(c[3])
        : "r"(a[0]), "r"(a[1]), "r"(a[2]), "r"(a[3]),
          "r"(b[0]), "r"(b[1]));
}

// ===========================================================================
// LayerNorm (one block/row, 128 thr) -> fp16 output.
// Blocks 0..1023 additionally round the 4 weight matrices into g_wr (fp16).
// ===========================================================================
__global__ void ln_kernel(const float* __restrict__ h,
                          const float* __restrict__ w,
                          const float* __restrict__ b,
                          __half* __restrict__ out,
                          const float* __restrict__ w0,
                          const float* __restrict__ w1,
                          const float* __restrict__ w2,
                          const float* __restrict__ w3,
                          __half* __restrict__ wr)
{
    int row = blockIdx.x;
    int t = threadIdx.x;

    if (row < 1024) {
        #pragma unroll
        for (int j = 0; j < 2; j++) {
            int idx = row * 256 + j * 128 + t;      // float4 index, 0..262143
            int mat = idx >> 16;
            int off = idx & 65535;
            const float* src = (mat == 0) ? w0 : (mat == 1) ? w1
                             : (mat == 2) ? w2 : w3;
            float4 v = ((const float4*)src)[off];
            uint2 u;
            u.x = pack_h2(v.x, v.y);
            u.y = pack_h2(v.z, v.w);
            ((uint2*)wr)[(size_t)mat * 65536 + off] = u;
        }
    }

    const float4* hr = (const float4*)(h + (size_t)row * D_DIM);
    float4 x = hr[t];
    float s  = x.x + x.y + x.z + x.w;
    float ss = x.x * x.x + x.y * x.y + x.z * x.z + x.w * x.w;

    #pragma unroll
    for (int o = 16; o; o >>= 1) {
        s  += __shfl_xor_sync(0xffffffffu, s,  o);
        ss += __shfl_xor_sync(0xffffffffu, ss, o);
    }
    __shared__ float red[2][4];
    int lane = t & 31, warp = t >> 5;
    if (lane == 0) { red[0][warp] = s; red[1][warp] = ss; }
    __syncthreads();
    float a = red[0][0] + red[0][1] + red[0][2] + red[0][3];
    float c = red[1][0] + red[1][1] + red[1][2] + red[1][3];
    float mean = a * (1.0f / D_DIM);
    float var  = c * (1.0f / D_DIM) - mean * mean;
    float rstd = rsqrtf(var + 1e-5f);

    float4 wv = ((const float4*)w)[t];
    float4 bv = ((const float4*)b)[t];
    uint2 u;
    u.x = pack_h2((x.x - mean) * rstd * wv.x + bv.x,
                  (x.y - mean) * rstd * wv.y + bv.y);
    u.y = pack_h2((x.z - mean) * rstd * wv.z + bv.z,
                  (x.w - mean) * rstd * wv.w + bv.w);
    *(uint2*)(out + (size_t)row * D_DIM + t * 4) = u;
}

// ===========================================================================
// Wv transpose: wvt[j][i] = fp16(Wv[i][j])  (512x512)
// ===========================================================================
__global__ void wv_transpose(const float* __restrict__ wv, __half* __restrict__ wvt)
{
    __shared__ float tile[32][33];
    int x0 = blockIdx.x * 32;
    int y0 = blockIdx.y * 32;
    int tx = threadIdx.x & 31, ty = threadIdx.x >> 5;   // 32 x 8
    #pragma unroll
    for (int i = 0; i < 32; i += 8)
        tile[ty + i][tx] = wv[(size_t)(y0 + ty + i) * D_DIM + x0 + tx];
    __syncthreads();
    #pragma unroll
    for (int i = 0; i < 32; i += 8)
        wvt[(size_t)(x0 + ty + i) * D_DIM + y0 + tx] = __float2half_rn(tile[tx][ty + i]);
}

// ===========================================================================
// Final: out = sum of 4 PV partials (z=0 partial already contains +h)
// ===========================================================================
__global__ void reduce_out(const float* __restrict__ avp,
                           float* __restrict__ out)
{
    int i = blockIdx.x * 256 + threadIdx.x;
    const size_t Np = (size_t)T_DIM * D_DIM / 4;
    const float4* p = (const float4*)avp;
    float4 a = p[i], b = p[i + Np], c = p[i + 2 * Np], d = p[i + 3 * Np];
    float4 o;
    o.x = (a.x + b.x) + (c.x + d.x);
    o.y = (a.y + b.y) + (c.y + d.y);
    o.z = (a.z + b.z) + (c.z + d.z);
    o.w = (a.w + b.w) + (c.w + d.w);
    ((float4*)out)[i] = o;
}

// ===========================================================================
// FP16 mma.sync GEMM (NT): C = scale*(A[M,K] @ B[N,K]^T)
// 128x128x64 block tile, 4 warps (2x2), warp 64x64, 2 CTA/SM,
// 3-stage cp.async ring, SW128 swizzle, ldmatrix, m16n8k16 fp32-acc.
//   CAUSAL:  skip blocks above diagonal; DIAGONAL blocks write NEG_BIG
//   CAPK:    cap k-loop at m0+128 (PV); reverses y-order (big CTAs first)
//   OUTH:    fp16 output; else fp32
//   KSPLIT>0: split capped k-range across blockIdx.z -> Cf + z*M*ldc;
//            z==0 partial adds residual res (if non-null)
//   QKV:     blockIdx.z in {0,1} selects weight B+z*D*D and output {Ch,C2h};
//            z==0 applies scale (Q/sqrt(d))
//   TRANSC:  write OUTPUT TRANSPOSED fp16 (C[n][m], row stride ldct)
// ===========================================================================
#define BK 64
#define TILE_B (128 * 128)       // 16 KB per tile buffer
#define NSTAGE 3
#define SM_A 0
#define SM_B (NSTAGE * TILE_B)
#define SM_TOT (2 * NSTAGE * TILE_B)   // 96 KB

template<int CAUSAL, int CAPK, int OUTH, int KSPLIT, int QKV, int TRANSC>
__global__ void __launch_bounds__(128, 2)
gemm_f16(const __half* __restrict__ A,
         const __half* __restrict__ B,
         __half* __restrict__ Ch,
         __half* __restrict__ C2h,
         float* __restrict__ Cf,
         const float* __restrict__ res,
         int M, int N, int K,
         int lda, int ldb, int ldc, int ldct,
         float scale)
{
    extern __shared__ char smem[];
    int yb = CAPK ? ((int)gridDim.y - 1 - (int)blockIdx.y) : (int)blockIdx.y;
    int m0 = yb * 128;
    int n0 = blockIdx.x * 128;
    if (CAUSAL && n0 > m0 + 127) return;

    const __half* Bp = B;
    __half* Chp = Ch;
    float* Cfp = Cf;
    int ldcw = ldc;
    float sc = scale;
    if (QKV) {
        int zq = blockIdx.z;
        Bp = B + (size_t)zq * D_DIM * D_DIM;
        Chp = (zq == 0) ? Ch : C2h;
        if (zq != 0) sc = 1.0f;       // scale only applies to Q
    }
    if (TRANSC) ldcw = ldct;

    uint32_t sbase = smem_u32(smem);
    int t    = threadIdx.x;
    int lane = t & 31;
    int warp = t >> 5;
    int gid  = lane >> 2;
    int tig  = lane & 3;
    int wm   = (warp >> 1) * 64;
    int wn   = (warp & 1) * 64;

    int kend  = CAPK ? min(K, m0 + 128) : K;
    int iters = kend / BK;
    int it0 = 0, it1 = iters;
    if (KSPLIT > 0) {
        int z = blockIdx.z;
        it0 = (iters * z) / KSPLIT;
        it1 = (iters * (z + 1)) / KSPLIT;
        Cfp = Cf + (size_t)z * M * ldc;
    }
    int niter = it1 - it0;

    auto load_tiles = [&](int buf, int k0) {
        #pragma unroll
        for (int i = 0; i < 8; i++) {
            int f = t + i * 128;
            int row = f >> 3, kg = f & 7;
            uint32_t off = SW128((uint32_t)(row * 128 + kg * 16));
            CP_ASYNC16(sbase + SM_A + buf * TILE_B + off,
                       A + (size_t)(m0 + row) * lda + k0 + kg * 8);
        }
        #pragma unroll
        for (int i = 0; i < 8; i++) {
            int f = t + i * 128;
            int row = f >> 3, kg = f & 7;
            uint32_t off = SW128((uint32_t)(row * 128 + kg * 16));
            CP_ASYNC16(sbase + SM_B + buf * TILE_B + off,
                       Bp + (size_t)(n0 + row) * ldb + k0 + kg * 8);
        }
    };

    float acc[4][8][4];
    #pragma unroll
    for (int mi = 0; mi < 4; mi++)
        #pragma unroll
        for (int ni = 0; ni < 8; ni++)
            #pragma unroll
            for (int r = 0; r < 4; r++) acc[mi][ni][r] = 0.0f;

    int q   = lane >> 3;
    int r8  = lane & 7;
    int aq1 = (q & 1) * 8;
    int aq2 = q >> 1;
    int bq1 = (q >> 1) * 8;
    int bq2 = q & 1;

    load_tiles(0, it0 * BK);
    CP_COMMIT();
    if (niter > 1) load_tiles(1, (it0 + 1) * BK);
    CP_COMMIT();

    int buf = 0;
    for (int it = 0; it < niter; it++) {
        CP_WAIT1();
        __syncthreads();

        uint32_t sa = sbase + SM_A + buf * TILE_B;
        uint32_t sb = sbase + SM_B + buf * TILE_B;

        int nx = it + 2;
        int nbuf = buf + 2; if (nbuf >= NSTAGE) nbuf -= NSTAGE;
        if (nx < niter) load_tiles(nbuf, (it0 + nx) * BK);
        CP_COMMIT();

        #pragma unroll
        for (int ks = 0; ks < BK / 16; ks++) {
            uint32_t afr[4][4];
            #pragma unroll
            for (int mi = 0; mi < 4; mi++) {
                int row = wm + mi * 16 + aq1 + r8;
                int kg  = 2 * ks + aq2;
                uint32_t addr = sa + (uint32_t)(row * 128) + (uint32_t)((kg ^ r8) * 16);
                ldsm_x4(afr[mi][0], afr[mi][1], afr[mi][2], afr[mi][3], addr);
            }
            uint32_t bfr[8][2];
            #pragma unroll
            for (int p = 0; p < 4; p++) {
                int row = wn + p * 16 + bq1 + r8;
                int kg  = 2 * ks + bq2;
                uint32_t addr = sb + (uint32_t)(row * 128) + (uint32_t)((kg ^ r8) * 16);
                uint32_t r0, r1, r2, r3;
                ldsm_x4(r0, r1, r2, r3, addr);
                bfr[2 * p][0] = r0; bfr[2 * p][1] = r1;
                bfr[2 * p + 1][0] = r2; bfr[2 * p + 1][1] = r3;
            }
            #pragma unroll
            for (int mi = 0; mi < 4; mi++)
                #pragma unroll
                for (int ni = 0; ni < 8; ni++)
                    mma_f16(acc[mi][ni], afr[mi], bfr[ni]);
        }

        buf++; if (buf >= NSTAGE) buf = 0;
    }

    if (TRANSC) {
        // Transposed fp16 output (vt)
        __syncthreads();
        float* st = (float*)smem;        // 128 x stride 132
        #pragma unroll
        for (int mi = 0; mi < 4; mi++) {
            #pragma unroll
            for (int ni = 0; ni < 8; ni++) {
                int row = wm + mi * 16 + gid;
                int col = wn + ni * 8 + tig * 2;
                st[(col + 0) * 132 + row]     = acc[mi][ni][0];
                st[(col + 1) * 132 + row]     = acc[mi][ni][1];
                st[(col + 0) * 132 + row + 8] = acc[mi][ni][2];
                st[(col + 1) * 132 + row + 8] = acc[mi][ni][3];
            }
        }
        __syncthreads();
        #pragma unroll
        for (int i = 0; i < 16; i++) {
            int idx = t + i * 128;
            int d = idx >> 4;
            int j = idx & 15;
            const float* sp = &st[d * 132 + j * 8];
            uint4 u;
            u.x = pack_h2(sp[0], sp[1]);
            u.y = pack_h2(sp[2], sp[3]);
            u.z = pack_h2(sp[4], sp[5]);
            u.w = pack_h2(sp[6], sp[7]);
            *(uint4*)(Chp + (size_t)(n0 + d) * ldcw + m0 + j * 8) = u;
        }
        return;
    }

    if (OUTH) {
        // fp16 output; on CAUSAL diagonal blocks, mask col>row with NEG_BIG
        bool diag = CAUSAL && (n0 == m0);
        #pragma unroll
        for (int mi = 0; mi < 4; mi++) {
            #pragma unroll
            for (int ni = 0; ni < 8; ni++) {
                int row = m0 + wm + mi * 16 + gid;
                int col = n0 + wn + ni * 8 + tig * 2;
                float v00 = acc[mi][ni][0] * sc;
                float v01 = acc[mi][ni][1] * sc;
                float v10 = acc[mi][ni][2] * sc;
                float v11 = acc[mi][ni][3] * sc;
                if (diag) {
                    if (col > row)         v00 = NEG_BIG;
                    if (col + 1 > row)     v01 = NEG_BIG;
                    if (col > row + 8)     v10 = NEG_BIG;
                    if (col + 1 > row + 8) v11 = NEG_BIG;
                }
                *(uint32_t*)(Chp + (size_t)row * ldcw + col)       = pack_h2(v00, v01);
                *(uint32_t*)(Chp + (size_t)(row + 8) * ldcw + col) = pack_h2(v10, v11);
            }
        }
        return;
    }

    // fp32 output (PV partials, raw; z=0 adds residual)
    bool addres = (KSPLIT > 0) && (blockIdx.z == 0) && (res != nullptr);
    #pragma unroll
    for (int mi = 0; mi < 4; mi++) {
        #pragma unroll
        for (int ni = 0; ni < 8; ni++) {
            int row = m0 + wm + mi * 16 + gid;
            int col = n0 + wn + ni * 8 + tig * 2;
            float2 o0, o1;
            o0.x = acc[mi][ni][0]; o0.y = acc[mi][ni][1];
            o1.x = acc[mi][ni][2]; o1.y = acc[mi][ni][3];
            size_t i0 = (size_t)row * ldcw + col;
            size_t i1 = (size_t)(row + 8) * ldcw + col;
            if (addres) {
                float2 r0 = *(const float2*)(res + i0);
                float2 r1 = *(const float2*)(res + i1);
                o0.x += r0.x; o0.y += r0.y;
                o1.x += r1.x; o1.y += r1.y;
            }
            *(float2*)(Cfp + i0) = o0;
            *(float2*)(Cfp + i1) = o1;
        }
    }
}

// ===========================================================================
// Causal row softmax over fp16 S (in place), SINGLE PASS with constant shift.
// Masked entries are NEG_BIG -> exp underflows to exact 0.
// ===========================================================================
__device__ __forceinline__ float block_reduce_sum(float v)
{
    __shared__ float sm[8];
    #pragma unroll
    for (int o = 16; o; o >>= 1)
        v += __shfl_xor_sync(0xffffffffu, v, o);
    int lane = threadIdx.x & 31, warp = threadIdx.x >> 5;
    if (lane == 0) sm[warp] = v;
    __syncthreads();
    float r = sm[0];
    #pragma unroll
    for (int i = 1; i < 8; i++) r += sm[i];
    return r;
}

__global__ void softmax_causal(__half* __restrict__ S)
{
    int row = blockIdx.x;
    int t = threadIdx.x;                 // 0..255
    int zend = (row & ~127) + 128;       // zero-pad cap (= PV k-cap)
    uint4* Srow = (uint4*)(S + (size_t)row * T_DIM);   // 8 halves per uint4

    float x[4][8];
    float sum = 0.0f;
    #pragma unroll
    for (int it = 0; it < 4; it++) {
        int j0 = (it << 11) + t * 8;
        bool grp = (j0 < zend);          // group-uniform
        uint4 u = make_uint4(0, 0, 0, 0);
        if (grp) u = Srow[(it << 8) + t];
        float2 f0 = __half22float2(*(__half2*)&u.x);
        float2 f1 = __half22float2(*(__half2*)&u.y);
        float2 f2 = __half22float2(*(__half2*)&u.z);
        float2 f3 = __half22float2(*(__half2*)&u.w);
        x[it][0] = __expf((grp ? f0.x : NEG_BIG) - SM_SHIFT);
        x[it][1] = __expf((grp ? f0.y : NEG_BIG) - SM_SHIFT);
        x[it][2] = __expf((grp ? f1.x : NEG_BIG) - SM_SHIFT);
        x[it][3] = __expf((grp ? f1.y : NEG_BIG) - SM_SHIFT);
        x[it][4] = __expf((grp ? f2.x : NEG_BIG) - SM_SHIFT);
        x[it][5] = __expf((grp ? f2.y : NEG_BIG) - SM_SHIFT);
        x[it][6] = __expf((grp ? f3.x : NEG_BIG) - SM_SHIFT);
        x[it][7] = __expf((grp ? f3.y : NEG_BIG) - SM_SHIFT);
        #pragma unroll
        for (int e = 0; e < 8; e++) sum += x[it][e];
    }
    sum = block_reduce_sum(sum);
    float inv = 1.0f / sum;

    #pragma unroll
    for (int it = 0; it < 4; it++) {
        int j0 = (it << 11) + t * 8;
        if (j0 < zend) {
            uint4 u;
            u.x = pack_h2(x[it][0] * inv, x[it][1] * inv);
            u.y = pack_h2(x[it][2] * inv, x[it][3] * inv);
            u.z = pack_h2(x[it][4] * inv, x[it][5] * inv);
            u.w = pack_h2(x[it][6] * inv, x[it][7] * inv);
            Srow[(it << 8) + t] = u;
        }
    }
}

// ===========================================================================
extern "C" void kernel_launch(void* const* d_in, const int* in_sizes, int n_in,
                              void* d_out, int out_size)
{
    const float* h    = (const float*)d_in[0];
    const float* ln_w = (const float*)d_in[1];
    const float* ln_b = (const float*)d_in[2];
    const float* w_q  = (const float*)d_in[3];
    const float* w_k  = (const float*)d_in[4];
    const float* w_v  = (const float*)d_in[5];
    const float* w_o  = (const float*)d_in[6];
    float* out = (float*)d_out;

    __half *hn, *q, *k, *vt, *S, *wr, *wvt;
    float *avp;
    cudaGetSymbolAddress((void**)&hn,  g_hnorm);
    cudaGetSymbolAddress((void**)&q,   g_q);
    cudaGetSymbolAddress((void**)&k,   g_k);
    cudaGetSymbolAddress((void**)&vt,  g_vt);
    cudaGetSymbolAddress((void**)&avp, g_avp);
    cudaGetSymbolAddress((void**)&S,   g_S);
    cudaGetSymbolAddress((void**)&wr,  g_wr);
    cudaGetSymbolAddress((void**)&wvt, g_wvt);
    __half* wp_r = wr + 2 * (size_t)D_DIM * D_DIM;   // W' slot
    __half* wo_r = wr + 3 * (size_t)D_DIM * D_DIM;   // Wo slot

    // One-time host-side resources (created on the correctness call, reused
    // under graph capture; device work is identical on every call).
    static cudaStream_t s2 = nullptr;
    static cudaEvent_t ev_fork = nullptr, ev_join = nullptr;
    if (s2 == nullptr) {
        cudaStreamCreateWithFlags(&s2, cudaStreamNonBlocking);
        cudaEventCreateWithFlags(&ev_fork, cudaEventDisableTiming);
        cudaEventCreateWithFlags(&ev_join, cudaEventDisableTiming);
    }

    cudaFuncSetAttribute((const void*)gemm_f16<0,0,1,0,1,0>,
                         cudaFuncAttributeMaxDynamicSharedMemorySize, SM_TOT);
    cudaFuncSetAttribute((const void*)gemm_f16<0,0,1,0,0,1>,
                         cudaFuncAttributeMaxDynamicSharedMemorySize, SM_TOT);
    cudaFuncSetAttribute((const void*)gemm_f16<1,0,1,0,0,0>,
                         cudaFuncAttributeMaxDynamicSharedMemorySize, SM_TOT);
    cudaFuncSetAttribute((const void*)gemm_f16<0,1,0,4,0,0>,
                         cudaFuncAttributeMaxDynamicSharedMemorySize, SM_TOT);
    cudaFuncSetAttribute((const void*)gemm_f16<0,0,1,0,0,0>,
                         cudaFuncAttributeMaxDynamicSharedMemorySize, SM_TOT);

    const float inv_sqrt_d = 0.044194173824159216f;  // 1/sqrt(512)

    // 1) LayerNorm -> fp16 (+ fused fp16 weight rounding into g_wr)
    ln_kernel<<<T_DIM, 128>>>(h, ln_w, ln_b, hn, w_q, w_k, w_v, w_o, wr);

    // ---- fork: side stream computes Wv^T -> W' -> V'^T while the main
    //      stream runs QK proj -> scores -> softmax ----
    cudaEventRecord(ev_fork, 0);
    cudaStreamWaitEvent(s2, ev_fork, 0);

    // side stream: Wv^T (fp16)
    dim3 gT(D_DIM / 32, D_DIM / 32);   // (16, 16)
    wv_transpose<<<gT, 256, 0, s2>>>(w_v, wvt);

    // side stream: W' = Wo @ Wv (NT) -> g_wr slot 2
    dim3 gWp(D_DIM / 128, D_DIM / 128);  // (4, 4)
    gemm_f16<0,0,1,0,0,0><<<gWp, 128, SM_TOT, s2>>>(wo_r, wvt,
        wp_r, nullptr, nullptr, nullptr,
        D_DIM, D_DIM, D_DIM, D_DIM, D_DIM, D_DIM, 0, 1.0f);

    // side stream: V'^T = (hn @ W'^T)^T (transposed epilogue)
    dim3 gVp(D_DIM / 128, T_DIM / 128);  // (4, 64)
    gemm_f16<0,0,1,0,0,1><<<gVp, 128, SM_TOT, s2>>>(hn, wp_r,
        vt, nullptr, nullptr, nullptr,
        T_DIM, D_DIM, D_DIM, D_DIM, D_DIM, 0, T_DIM, 1.0f);

    cudaEventRecord(ev_join, s2);

    // main stream: Q (pre-scaled by 1/sqrt(d)) and K projections
    dim3 gQK(D_DIM / 128, T_DIM / 128, 2);  // (4, 64, 2)
    gemm_f16<0,0,1,0,1,0><<<gQK, 128, SM_TOT>>>(hn, wr,
        q, k, nullptr, nullptr,
        T_DIM, D_DIM, D_DIM, D_DIM, D_DIM, D_DIM, 0, inv_sqrt_d);

    // main stream: Scores = Q @ K^T -> fp16 S; diagonal blocks pre-masked
    dim3 gScore(T_DIM / 128, T_DIM / 128);  // (64, 64)
    gemm_f16<1,0,1,0,0,0><<<gScore, 128, SM_TOT>>>(q, k,
        S, nullptr, nullptr, nullptr,
        T_DIM, T_DIM, D_DIM, D_DIM, D_DIM, T_DIM, 0, 1.0f);

    // main stream: causal softmax (single pass, constant shift)
    softmax_causal<<<T_DIM, 256>>>(S);

    // ---- join: PV needs vt from the side stream ----
    cudaStreamWaitEvent(0, ev_join, 0);

    // 5) AV' partials = softmax(S) @ V'^T (k-capped, split-K4; z=0 adds h)
    dim3 gPV(D_DIM / 128, T_DIM / 128, 4);  // (4, 64, 4)
    gemm_f16<0,1,0,4,0,0><<<gPV, 128, SM_TOT>>>(S, vt,
        nullptr, nullptr, avp, h,
        T_DIM, D_DIM, T_DIM, T_DIM, T_DIM, D_DIM, 0, 1.0f);

    // 6) out = sum of 4 partials (h already inside z=0 partial)
    reduce_out<<<(T_DIM * D_DIM) / 4 / 256, 256>>>(avp, out);
}